// round 12
// baseline (speedup 1.0000x reference)
#include <cuda_runtime.h>
#include <cuda_bf16.h>
#include <cuda_fp16.h>
#include <math.h>
#include <stdint.h>

// ---------------- problem constants ----------------
#define N_ROWS   131072
#define DIM      256
#define K_CODES  1024
#define EPS_F    1e-5f
#define TAU_F    3.5e-4f
#define CAND_W   6.0e-4f
#define FIX_CAP  131072

// output layout (float32 elements), reference return order
#define OFF_Q       0
#define OFF_LOSS    33554432
#define OFF_IDX     33554433
#define OFF_NEWEMB  33685505
#define OFF_NCS     33947649
#define OFF_NAVG    33948673

// ---------------- device scratch ----------------
__device__ float  g_xx[N_ROWS];
__device__ float  g_ee[K_CODES];
__device__ float  g_counts[K_CODES];
__device__ float  g_embsum[K_CODES*DIM];
__device__ float  g_ncs[K_CODES];
__device__ float  g_ntotal;
__device__ double g_sse;
__device__ double g_ortho;
__device__ int    g_fixcount;
__device__ int    g_fixrows[FIX_CAP];
__device__ int    g_idx[N_ROWS];
__device__ int    g_cnt_i[K_CODES];
__device__ int    g_off[K_CODES];
__device__ int    g_cursor[K_CODES];
__device__ int    g_rowlist[N_ROWS];
__device__ __nv_bfloat16 g_ea[K_CODES*DIM];
__device__ __half g_sc[(size_t)N_ROWS*K_CODES];   // screened scores, fp16

// ---------------- PTX helpers (baseline sm_80+ ISA only) ----------------
__device__ __forceinline__ uint32_t smem_to_u32(const void* p) {
    uint32_t a;
    asm("{ .reg .u64 t; cvta.to.shared.u64 t, %1; cvt.u32.u64 %0, t; }" : "=r"(a) : "l"(p));
    return a;
}
#define CP_ASYNC16(dst, src) \
    asm volatile("cp.async.cg.shared.global [%0], [%1], 16;" :: "r"(dst), "l"(src))
#define CP_COMMIT() asm volatile("cp.async.commit_group;" ::: "memory")
#define CP_WAIT1()  asm volatile("cp.async.wait_group 1;" ::: "memory")

#define LDSM_X4(r, addr) \
    asm volatile("ldmatrix.sync.aligned.m8n8.x4.shared.b16 {%0,%1,%2,%3}, [%4];" \
        : "=r"((r)[0]), "=r"((r)[1]), "=r"((r)[2]), "=r"((r)[3]) : "r"(addr))

#define MMA_BF16(c, a, b0, b1) \
    asm volatile("mma.sync.aligned.m16n8k16.row.col.f32.bf16.bf16.f32 " \
        "{%0,%1,%2,%3},{%4,%5,%6,%7},{%8,%9},{%0,%1,%2,%3};" \
        : "+f"((c)[0]), "+f"((c)[1]), "+f"((c)[2]), "+f"((c)[3]) \
        : "r"((a)[0]), "r"((a)[1]), "r"((a)[2]), "r"((a)[3]), "r"(b0), "r"(b1))

__device__ __forceinline__ uint32_t packhi2(float x, float y) {
    __nv_bfloat16 a = __float2bfloat16_rn(x);
    __nv_bfloat16 b = __float2bfloat16_rn(y);
    return (uint32_t)__bfloat16_as_ushort(a) | ((uint32_t)__bfloat16_as_ushort(b) << 16);
}

// ---------------- prep codes: zero scratch (block 0) + ||e||^2 + bf16 copy ----------------
__global__ void prep_e_kernel(const float* __restrict__ emb) {
    if (blockIdx.x == 0) {
        for (int i = threadIdx.x; i < K_CODES; i += 256) g_cnt_i[i] = 0;
        if (threadIdx.x == 0) { g_sse = 0.0; g_ortho = 0.0; g_fixcount = 0; }
    }
    int warp = (blockIdx.x * blockDim.x + threadIdx.x) >> 5;
    int lane = threadIdx.x & 31;
    if (warp >= K_CODES) return;
    const float4* p = (const float4*)(emb + (size_t)warp * DIM);
    float4 v0 = p[lane * 2];
    float4 v1 = p[lane * 2 + 1];
    float s = 0.f;
    s = fmaf(v0.x,v0.x,s); s = fmaf(v0.y,v0.y,s); s = fmaf(v0.z,v0.z,s); s = fmaf(v0.w,v0.w,s);
    s = fmaf(v1.x,v1.x,s); s = fmaf(v1.y,v1.y,s); s = fmaf(v1.z,v1.z,s); s = fmaf(v1.w,v1.w,s);
    uint4 hi;
    hi.x = packhi2(v0.x, v0.y);
    hi.y = packhi2(v0.z, v0.w);
    hi.z = packhi2(v1.x, v1.y);
    hi.w = packhi2(v1.z, v1.w);
    ((uint4*)(g_ea + (size_t)warp * DIM))[lane] = hi;
    #pragma unroll
    for (int o = 16; o > 0; o >>= 1) s += __shfl_xor_sync(0xffffffffu, s, o);
    if (lane == 0) g_ee[warp] = s;
}

// ---------------- HMMA GEMM, 512 threads, in-kernel X convert, E-only stages ----------------
// smem: XRES[4 kc][128 rows][64 dims] @0 (64K) | E buf0/1 @65536+buf*32768 ([2 kcs][128][64])
// stage s (0..15): n0 = s>>1 (code group of 128), kc2 = s&1 (dims kc2*128..+128)
#define OFB_E  65536
#define E_STRIDE 32768
#define STG_OFF 131072                  // score staging: 128 rows x 272B
#define SMEM_DYN (STG_OFF + 128*272 + 1024)

__device__ __forceinline__ void load_e_stage(uint32_t sbase, int st, int tid) {
    int n0 = st >> 1, kc2 = st & 1;
    uint32_t ebase = sbase + OFB_E + (uint32_t)(st & 1) * E_STRIDE;
    const __nv_bfloat16* ea = g_ea + ((size_t)(n0 * 128) << 8) + kc2 * 128;
    #pragma unroll
    for (int it = 0; it < 4; it++) {
        int idx = tid + it * 512;           // 0..2047
        int kcs = idx >> 10;                // sub-chunk 0/1
        int rem = idx & 1023;
        int r = rem >> 3, kb = rem & 7;
        uint32_t sw = (((uint32_t)kb * 16u) ^ (((uint32_t)r & 7u) * 16u));
        uint32_t d  = ebase + (uint32_t)kcs * 16384u + (uint32_t)r * 128u + sw;
        CP_ASYNC16(d, ea + (size_t)r * DIM + kcs * 64 + kb * 8);
    }
}

// convert 128 rows of X fp32 -> bf16 into resident smem + compute g_xx
// thread = row*4 + q : handles dims q*64 .. q*64+63 of row
__device__ __forceinline__ void convert_x_res(char* smema, const float* __restrict__ inp,
                                              int R0, int tid) {
    int row = tid >> 2, q = tid & 3;
    const float4* xr = (const float4*)(inp + (size_t)(R0 + row) * DIM + q * 64);
    char* base = smema + (uint32_t)q * 16384u + (uint32_t)row * 128u;
    float s = 0.f;
    #pragma unroll
    for (int j = 0; j < 8; j++) {
        float4 a = xr[j * 2], b = xr[j * 2 + 1];
        s = fmaf(a.x,a.x,s); s = fmaf(a.y,a.y,s); s = fmaf(a.z,a.z,s); s = fmaf(a.w,a.w,s);
        s = fmaf(b.x,b.x,s); s = fmaf(b.y,b.y,s); s = fmaf(b.z,b.z,s); s = fmaf(b.w,b.w,s);
        uint4 hi;
        hi.x = packhi2(a.x, a.y);
        hi.y = packhi2(a.z, a.w);
        hi.z = packhi2(b.x, b.y);
        hi.w = packhi2(b.z, b.w);
        uint32_t sw = (((uint32_t)j * 16u) ^ (((uint32_t)row & 7u) * 16u));
        *(uint4*)(base + sw) = hi;
    }
    s += __shfl_xor_sync(0xffffffffu, s, 1);
    s += __shfl_xor_sync(0xffffffffu, s, 2);
    if (q == 0) g_xx[R0 + row] = s;
}

__global__ void __launch_bounds__(512, 1)
hmma_gemm_kernel(const float* __restrict__ inp)
{
    extern __shared__ __align__(16) char dsm[];
    uint32_t raw   = smem_to_u32(dsm);
    uint32_t sbase = (raw + 1023u) & ~1023u;
    char*    smema = dsm + (sbase - raw);

    const int tid  = threadIdx.x;
    const int lane = tid & 31, wid = tid >> 5;
    const int wr   = wid >> 2, wc = wid & 3;    // wr: 32-row group, wc: 32-code group
    const int R0   = blockIdx.x * 128;
    const int g    = lane >> 2, tig = lane & 3;
    const int q    = lane >> 3, lr  = lane & 7;

    float acc[2][4][4];
    #pragma unroll
    for (int a = 0; a < 2; a++)
        #pragma unroll
        for (int b = 0; b < 4; b++)
            #pragma unroll
            for (int c = 0; c < 4; c++) acc[a][b][c] = 0.f;

    float rs1[4], rs2[4]; int ri[4];
    #pragma unroll
    for (int j = 0; j < 4; j++) { rs1[j] = 3.0e38f; rs2[j] = 3.0e38f; ri[j] = 0x7fffffff; }

    uint32_t* stage_w = (uint32_t*)(smema + STG_OFF);   // row stride = 68 words (272B)

    load_e_stage(sbase, 0, tid);
    CP_COMMIT();                   // group 0: E0 (in flight during X conversion)
    convert_x_res(smema, inp, R0, tid);

    for (int s = 0; s < 16; s++) {
        if (s + 1 < 16) load_e_stage(sbase, s + 1, tid);
        CP_COMMIT();
        CP_WAIT1();                // stage s resident
        __syncthreads();           // also publishes X st.shared on first iteration

        const int kc2 = s & 1;
        uint32_t ebase = sbase + OFB_E + (uint32_t)(s & 1) * E_STRIDE;
        #pragma unroll
        for (int kcs = 0; kcs < 2; kcs++) {
            uint32_t xbase = sbase + (uint32_t)(kc2 * 2 + kcs) * 16384u;
            uint32_t ecb   = ebase + (uint32_t)kcs * 16384u;
            #pragma unroll
            for (int ks = 0; ks < 4; ks++) {
                uint32_t axa[8];
                int rowb = wr * 32 + lr + ((q & 1) << 3);
                int kbA  = ks * 2 + (q >> 1);
                uint32_t swA = (((uint32_t)kbA * 16u) ^ ((uint32_t)lr * 16u));
                #pragma unroll
                for (int mf = 0; mf < 2; mf++) {
                    uint32_t ad = xbase + (uint32_t)(rowb + mf * 16) * 128u + swA;
                    LDSM_X4(&axa[mf * 4], ad);
                }
                uint32_t bea[8];
                int kbB = ks * 2 + (q & 1);
                uint32_t swB = (((uint32_t)kbB * 16u) ^ ((uint32_t)lr * 16u));
                #pragma unroll
                for (int np = 0; np < 2; np++) {
                    int code = wc * 32 + np * 16 + lr + ((q >> 1) << 3);
                    uint32_t ed = ecb + (uint32_t)code * 128u + swB;
                    LDSM_X4(&bea[np * 4], ed);
                }
                #pragma unroll
                for (int mf = 0; mf < 2; mf++)
                    #pragma unroll
                    for (int nf = 0; nf < 4; nf++) {
                        int bo = (nf >> 1) * 4 + (nf & 1) * 2;
                        MMA_BF16(acc[mf][nf], &axa[mf * 4], bea[bo], bea[bo + 1]);
                    }
            }
        }

        if (s & 1) {
            int n0 = s >> 1;
            float ee8[8];
            #pragma unroll
            for (int nf = 0; nf < 4; nf++) {
                int code = n0 * 128 + wc * 32 + nf * 8 + tig * 2;
                ee8[nf * 2]     = __ldg(&g_ee[code]);
                ee8[nf * 2 + 1] = __ldg(&g_ee[code + 1]);
            }
            #pragma unroll
            for (int mf = 0; mf < 2; mf++)
                #pragma unroll
                for (int h = 0; h < 2; h++) {
                    int j = mf * 2 + h;
                    int row = wr * 32 + mf * 16 + h * 8 + g;
                    float b1 = 3.0e38f, b2 = 3.0e38f; int bi = 0;
                    #pragma unroll
                    for (int nf = 0; nf < 4; nf++) {
                        int code = n0 * 128 + wc * 32 + nf * 8 + tig * 2;
                        float s0 = fmaf(-2.f, acc[mf][nf][h * 2],     ee8[nf * 2]);
                        float s1 = fmaf(-2.f, acc[mf][nf][h * 2 + 1], ee8[nf * 2 + 1]);
                        __half2 hv = __floats2half2_rn(s0, s1);
                        stage_w[row * 68 + wc * 16 + nf * 4 + tig] = *(uint32_t*)&hv;
                        if (s0 < b1) { b2 = b1; b1 = s0; bi = code; }
                        else if (s0 < b2) b2 = s0;
                        if (s1 < b1) { b2 = b1; b1 = s1; bi = code + 1; }
                        else if (s1 < b2) b2 = s1;
                    }
                    #pragma unroll
                    for (int off = 1; off <= 2; off <<= 1) {
                        float o1 = __shfl_xor_sync(0xffffffffu, b1, off);
                        float o2 = __shfl_xor_sync(0xffffffffu, b2, off);
                        int   oi = __shfl_xor_sync(0xffffffffu, bi, off);
                        if (o1 < b1) { b2 = fminf(b1, o2); b1 = o1; bi = oi; }
                        else         { b2 = fminf(b2, o1); }
                    }
                    if (b1 < rs1[j]) { rs2[j] = fminf(rs1[j], b2); rs1[j] = b1; ri[j] = bi; }
                    else             { rs2[j] = fminf(rs2[j], b1); }
                }
            __syncthreads();
            // coalesced copy staging -> g_sc[row][n0*128 .. +128)
            #pragma unroll
            for (int it = 0; it < 4; it++) {
                int idx = tid + it * 512;          // 0..2047
                int row = idx >> 4, seg = idx & 15;
                uint4 v = *(const uint4*)(smema + STG_OFF + row * 272 + seg * 16);
                *(uint4*)((char*)(g_sc + (size_t)(R0 + row) * K_CODES + n0 * 128) + seg * 16) = v;
            }
            #pragma unroll
            for (int a = 0; a < 2; a++)
                #pragma unroll
                for (int b = 0; b < 4; b++)
                    #pragma unroll
                    for (int c = 0; c < 4; c++) acc[a][b][c] = 0.f;
        }
        __syncthreads();
    }

    // final cross-warp merge (alias XRES smem; all MMA work done)
    float* fs1 = (float*)smema;
    float* fs2 = (float*)(smema + 2048);
    int*   fi1 = (int*)  (smema + 4096);
    #pragma unroll
    for (int mf = 0; mf < 2; mf++)
        #pragma unroll
        for (int h = 0; h < 2; h++) {
            int j = mf * 2 + h;
            int row = wr * 32 + mf * 16 + h * 8 + g;
            fs1[row * 4 + wc] = rs1[j];
            fs2[row * 4 + wc] = rs2[j];
            fi1[row * 4 + wc] = ri[j];
        }
    __syncthreads();
    if (tid < 128) {
        float b1 = 3.0e38f, b2 = 3.0e38f; int bi = 0;
        #pragma unroll
        for (int w = 0; w < 4; w++) {
            float o1 = fs1[tid * 4 + w], o2 = fs2[tid * 4 + w];
            int   oi = fi1[tid * 4 + w];
            if (o1 < b1) { b2 = fminf(b1, o2); b1 = o1; bi = oi; }
            else         { b2 = fminf(b2, o1); }
        }
        g_idx[R0 + tid] = bi;
        atomicAdd(&g_cnt_i[bi], 1);                 // tentative histogram
        if (b2 - b1 < TAU_F) {
            int p = atomicAdd(&g_fixcount, 1);
            if (p < FIX_CAP) g_fixrows[p] = R0 + tid;
        }
    }
}

// ---------------- candidate rescore: warp per flagged row, exact fp32 on few codes ----------------
__global__ void __launch_bounds__(256)
rescore2_kernel(const float* __restrict__ inp, const float* __restrict__ emb)
{
    int n = g_fixcount; if (n > FIX_CAP) n = FIX_CAP;
    int gw   = (blockIdx.x * 256 + threadIdx.x) >> 5;
    int lane = threadIdx.x & 31;
    const int NW = (1024 * 256) >> 5;

    for (int fi = gw; fi < n; fi += NW) {
        int row = g_fixrows[fi];
        const __half* sc = g_sc + (size_t)row * K_CODES;

        float m = 3.0e38f;
        #pragma unroll
        for (int it = 0; it < 4; it++) {
            uint4 v = ((const uint4*)sc)[it * 32 + lane];
            const __half2* h = (const __half2*)&v;
            #pragma unroll
            for (int j = 0; j < 4; j++) {
                float2 f = __half22float2(h[j]);
                m = fminf(m, fminf(f.x, f.y));
            }
        }
        #pragma unroll
        for (int o = 16; o > 0; o >>= 1) m = fminf(m, __shfl_xor_sync(0xffffffffu, m, o));
        float thr = m + CAND_W;

        const float4* xr = (const float4*)(inp + (size_t)row * DIM);
        float4 xa = xr[lane * 2], xb = xr[lane * 2 + 1];
        float xx = g_xx[row];

        float bd = 3.0e38f; int bi = 0x7fffffff;
        for (int ci = 0; ci < 32; ci++) {
            float sv = __half2float(sc[ci * 32 + lane]);
            unsigned mask = __ballot_sync(0xffffffffu, sv <= thr);
            while (mask) {
                int b_ = __ffs(mask) - 1; mask &= mask - 1;
                int cc = ci * 32 + b_;
                const float4* er = (const float4*)(emb + (size_t)cc * DIM);
                float4 e0 = er[lane * 2], e1 = er[lane * 2 + 1];
                float d = 0.f;
                d = fmaf(e0.x, xa.x, d); d = fmaf(e0.y, xa.y, d);
                d = fmaf(e0.z, xa.z, d); d = fmaf(e0.w, xa.w, d);
                d = fmaf(e1.x, xb.x, d); d = fmaf(e1.y, xb.y, d);
                d = fmaf(e1.z, xb.z, d); d = fmaf(e1.w, xb.w, d);
                #pragma unroll
                for (int o = 16; o > 0; o >>= 1) d += __shfl_xor_sync(0xffffffffu, d, o);
                float dist = (xx + g_ee[cc]) - 2.0f * d;
                if (dist < bd || (dist == bd && cc < bi)) { bd = dist; bi = cc; }
            }
        }
        if (lane == 0) {
            int old = g_idx[row];
            if (bi != old) {
                g_idx[row] = bi;
                atomicAdd(&g_cnt_i[old], -1);
                atomicAdd(&g_cnt_i[bi], 1);
            }
        }
    }
}

// ---------------- offsets ----------------
__global__ void offsets_kernel() {
    __shared__ int tmp[2][1024];
    int t = threadIdx.x;
    int v = g_cnt_i[t];
    g_counts[t] = (float)v;
    tmp[0][t] = v;
    __syncthreads();
    int src = 0;
    #pragma unroll
    for (int d = 1; d < 1024; d <<= 1) {
        int nv = tmp[src][t] + (t >= d ? tmp[src][t - d] : 0);
        tmp[src ^ 1][t] = nv;
        src ^= 1;
        __syncthreads();
    }
    int off = tmp[src][t] - v;   // exclusive
    g_off[t] = off;
    g_cursor[t] = off;
}

// ---------------- epilogue: gather + Q/idx output + MSE + rowlist scatter ----------------
__global__ void __launch_bounds__(256)
epilogue_kernel(const float* __restrict__ inp, const float* __restrict__ emb,
                float* __restrict__ out)
{
    __shared__ int besti[128];
    __shared__ double dred[256];
    const int tid = threadIdx.x;
    const int R0  = blockIdx.x * 128;
    if (tid < 128) {
        int v = g_idx[R0 + tid];
        besti[tid] = v;
        out[OFF_IDX + R0 + tid] = (float)v;
        int pos = atomicAdd(&g_cursor[v], 1);      // fused scatter
        g_rowlist[pos] = R0 + tid;
    }
    __syncthreads();

    float sse = 0.f;
    const float4* inp4 = (const float4*)inp;
    const float4* emb4 = (const float4*)emb;
    float4* out4 = (float4*)(out + OFF_Q);
    #pragma unroll 4
    for (int j = 0; j < 32; j++) {
        int e4  = tid + j * 256;
        int r   = e4 >> 6;
        int c4  = e4 & 63;
        int idx = besti[r];
        float4 ev = emb4[idx * 64 + c4];
        float4 xv = inp4[(size_t)(R0 + r) * 64 + c4];
        float4 qv;
        qv.x = xv.x + (ev.x - xv.x);
        qv.y = xv.y + (ev.y - xv.y);
        qv.z = xv.z + (ev.z - xv.z);
        qv.w = xv.w + (ev.w - xv.w);
        out4[(size_t)(R0 + r) * 64 + c4] = qv;
        float d0 = ev.x - xv.x, d1 = ev.y - xv.y, d2 = ev.z - xv.z, d3 = ev.w - xv.w;
        sse = fmaf(d0, d0, sse); sse = fmaf(d1, d1, sse);
        sse = fmaf(d2, d2, sse); sse = fmaf(d3, d3, sse);
    }
    dred[tid] = (double)sse;
    __syncthreads();
    #pragma unroll
    for (int s = 128; s > 0; s >>= 1) {
        if (tid < s) dred[tid] += dred[tid + s];
        __syncthreads();
    }
    if (tid == 0) atomicAdd(&g_sse, dred[0]);
}

// ---------------- segment-sum (after epilogue builds rowlist) ----------------
__global__ void __launch_bounds__(256)
segsum_kernel(const float* __restrict__ inp) {
    int k = blockIdx.x, t = threadIdx.x;
    int beg = g_off[k], cnt = g_cnt_i[k];
    float s = 0.f;
    int j = 0;
    for (; j + 4 <= cnt; j += 4) {
        int r0 = g_rowlist[beg + j],     r1 = g_rowlist[beg + j + 1];
        int r2 = g_rowlist[beg + j + 2], r3 = g_rowlist[beg + j + 3];
        float v0 = inp[(size_t)r0 * DIM + t];
        float v1 = inp[(size_t)r1 * DIM + t];
        float v2 = inp[(size_t)r2 * DIM + t];
        float v3 = inp[(size_t)r3 * DIM + t];
        s += v0; s += v1; s += v2; s += v3;
    }
    for (; j < cnt; j++) s += inp[(size_t)g_rowlist[beg + j] * DIM + t];
    g_embsum[k * DIM + t] = s;
}

// ---------------- ortho via ||E^T E||_F^2 ----------------
__global__ void gram_kernel(const float* __restrict__ emb) {
    __shared__ float sA[64][16];
    __shared__ float sB[64][16];
    __shared__ double sred[256];
    int tx = threadIdx.x & 15;
    int ty = threadIdx.x >> 4;
    int a0 = blockIdx.y * 16;
    int b0 = blockIdx.x * 16;
    float acc = 0.f;
    for (int k0 = 0; k0 < K_CODES; k0 += 64) {
        __syncthreads();
        #pragma unroll
        for (int i = 0; i < 4; i++) {
            int e = threadIdx.x + i * 256;
            int kr = e >> 4, c = e & 15;
            sA[kr][c] = emb[(size_t)(k0 + kr) * DIM + a0 + c];
            sB[kr][c] = emb[(size_t)(k0 + kr) * DIM + b0 + c];
        }
        __syncthreads();
        #pragma unroll 8
        for (int kk = 0; kk < 64; kk++)
            acc = fmaf(sA[kk][ty], sB[kk][tx], acc);
    }
    sred[threadIdx.x] = (double)acc * (double)acc;
    __syncthreads();
    #pragma unroll
    for (int s = 128; s > 0; s >>= 1) {
        if (threadIdx.x < s) sred[threadIdx.x] += sred[threadIdx.x + s];
        __syncthreads();
    }
    if (threadIdx.x == 0) atomicAdd(&g_ortho, sred[0]);
}

// ---------------- EMA finalize ----------------
__global__ void ema_a_kernel(const float* __restrict__ ema_cs, float* __restrict__ out) {
    __shared__ double sred[1024];
    int k = threadIdx.x;
    float ncs = 0.99f * ema_cs[k] + 0.01f * g_counts[k];
    out[OFF_NCS + k] = ncs;
    g_ncs[k] = ncs;
    sred[k] = (double)ncs;
    __syncthreads();
    #pragma unroll
    for (int s = 512; s > 0; s >>= 1) {
        if (k < s) sred[k] += sred[k + s];
        __syncthreads();
    }
    if (k == 0) g_ntotal = (float)sred[0] + EPS_F;
}
__global__ void ema_b_kernel(const float* __restrict__ ema_avg, float* __restrict__ out) {
    int k = blockIdx.x;
    int d = threadIdx.x;
    int i = k * DIM + d;
    float navg = 0.99f * ema_avg[i] + 0.01f * g_embsum[i];
    out[OFF_NAVG + i] = navg;
    float cs = (g_ncs[k] + EPS_F) / g_ntotal;
    out[OFF_NEWEMB + i] = navg / cs;
}

// ---------------- loss ----------------
__global__ void loss_fin_kernel(float* __restrict__ out) {
    __shared__ double sred[256];
    double s = 0.0;
    for (int k = threadIdx.x; k < K_CODES; k += 256) {
        double e = (double)g_ee[k];
        s += e * e;
    }
    sred[threadIdx.x] = s;
    __syncthreads();
    #pragma unroll
    for (int t = 128; t > 0; t >>= 1) {
        if (threadIdx.x < t) sred[threadIdx.x] += sred[threadIdx.x + t];
        __syncthreads();
    }
    if (threadIdx.x == 0) {
        double o2 = g_ortho - sred[0];
        if (o2 < 0.0) o2 = 0.0;
        float ortho = sqrtf((float)o2);
        float m = (float)(g_sse / (double)((size_t)N_ROWS * DIM));
        out[OFF_LOSS] = (m + 0.25f * m) + 0.09f * ortho;
    }
}

// ---------------- launch ----------------
extern "C" void kernel_launch(void* const* d_in, const int* in_sizes, int n_in,
                              void* d_out, int out_size)
{
    const float* inp     = (const float*)d_in[0];
    const float* emb     = (const float*)d_in[1];
    const float* ema_cs  = (const float*)d_in[2];
    const float* ema_avg = (const float*)d_in[3];
    float* out = (float*)d_out;

    static int inited = 0;
    static cudaStream_t s2;
    static cudaEvent_t ev_root, ev_pe, ev_side;
    if (!inited) {
        cudaFuncSetAttribute(hmma_gemm_kernel,
                             cudaFuncAttributeMaxDynamicSharedMemorySize, SMEM_DYN);
        cudaStreamCreateWithFlags(&s2, cudaStreamNonBlocking);
        cudaEventCreateWithFlags(&ev_root, cudaEventDisableTiming);
        cudaEventCreateWithFlags(&ev_pe,   cudaEventDisableTiming);
        cudaEventCreateWithFlags(&ev_side, cudaEventDisableTiming);
        inited = 1;
    }

    // fork side stream: prep_e + gram (independent of main chain until gemm/loss)
    cudaEventRecord(ev_root, 0);
    cudaStreamWaitEvent(s2, ev_root, 0);
    prep_e_kernel<<<K_CODES / 8, 256, 0, s2>>>(emb);
    cudaEventRecord(ev_pe, s2);
    gram_kernel<<<dim3(16, 16), 256, 0, s2>>>(emb);
    cudaEventRecord(ev_side, s2);

    cudaStreamWaitEvent(0, ev_pe, 0);          // gemm needs g_ea/g_ee/g_cnt_i
    hmma_gemm_kernel<<<N_ROWS / 128, 512, SMEM_DYN>>>(inp);
    rescore2_kernel<<<1024, 256>>>(inp, emb);
    offsets_kernel<<<1, 1024>>>();
    epilogue_kernel<<<N_ROWS / 128, 256>>>(inp, emb, out);
    segsum_kernel<<<K_CODES, 256>>>(inp);
    ema_a_kernel<<<1, 1024>>>(ema_cs, out);
    ema_b_kernel<<<K_CODES, 256>>>(ema_avg, out);
    cudaStreamWaitEvent(0, ev_side, 0);        // loss needs g_ortho
    loss_fin_kernel<<<1, 256>>>(out);
}

// round 13
// speedup vs baseline: 1.0128x; 1.0128x over previous
#include <cuda_runtime.h>
#include <cuda_bf16.h>
#include <cuda_fp16.h>
#include <math.h>
#include <stdint.h>

// ---------------- problem constants ----------------
#define N_ROWS   131072
#define DIM      256
#define K_CODES  1024
#define EPS_F    1e-5f
#define TAU_F    3.5e-4f
#define CAND_W   6.0e-4f
#define FIX_CAP  131072

// output layout (float32 elements), reference return order
#define OFF_Q       0
#define OFF_LOSS    33554432
#define OFF_IDX     33554433
#define OFF_NEWEMB  33685505
#define OFF_NCS     33947649
#define OFF_NAVG    33948673

// ---------------- device scratch ----------------
__device__ float  g_xx[N_ROWS];
__device__ float  g_ee[K_CODES];
__device__ float  g_counts[K_CODES];
__device__ float  g_embsum[K_CODES*DIM];
__device__ float  g_ncs[K_CODES];
__device__ float  g_ntotal;
__device__ double g_sse;
__device__ double g_ortho;
__device__ int    g_fixcount;
__device__ int    g_fixrows[FIX_CAP];
__device__ int    g_idx[N_ROWS];
__device__ int    g_cnt_i[K_CODES];
__device__ int    g_off[K_CODES];
__device__ int    g_cursor[K_CODES];
__device__ int    g_rowlist[N_ROWS];
__device__ __nv_bfloat16 g_ea[K_CODES*DIM];
__device__ __nv_bfloat16 g_xa[(size_t)N_ROWS*DIM];
__device__ __half g_sc[(size_t)N_ROWS*K_CODES];   // screened scores, fp16

// ---------------- PTX helpers (baseline sm_80+ ISA only) ----------------
__device__ __forceinline__ uint32_t smem_to_u32(const void* p) {
    uint32_t a;
    asm("{ .reg .u64 t; cvta.to.shared.u64 t, %1; cvt.u32.u64 %0, t; }" : "=r"(a) : "l"(p));
    return a;
}
#define CP_ASYNC16(dst, src) \
    asm volatile("cp.async.cg.shared.global [%0], [%1], 16;" :: "r"(dst), "l"(src))
#define CP_COMMIT() asm volatile("cp.async.commit_group;" ::: "memory")
#define CP_WAIT1()  asm volatile("cp.async.wait_group 1;" ::: "memory")

#define LDSM_X4(r, addr) \
    asm volatile("ldmatrix.sync.aligned.m8n8.x4.shared.b16 {%0,%1,%2,%3}, [%4];" \
        : "=r"((r)[0]), "=r"((r)[1]), "=r"((r)[2]), "=r"((r)[3]) : "r"(addr))

#define MMA_BF16(c, a, b0, b1) \
    asm volatile("mma.sync.aligned.m16n8k16.row.col.f32.bf16.bf16.f32 " \
        "{%0,%1,%2,%3},{%4,%5,%6,%7},{%8,%9},{%0,%1,%2,%3};" \
        : "+f"((c)[0]), "+f"((c)[1]), "+f"((c)[2]), "+f"((c)[3]) \
        : "r"((a)[0]), "r"((a)[1]), "r"((a)[2]), "r"((a)[3]), "r"(b0), "r"(b1))

#define STG_CS_V4(ptr, v) \
    asm volatile("st.global.cs.v4.u32 [%0], {%1,%2,%3,%4};" \
        :: "l"(ptr), "r"((v).x), "r"((v).y), "r"((v).z), "r"((v).w) : "memory")

__device__ __forceinline__ uint32_t packhi2(float x, float y) {
    __nv_bfloat16 a = __float2bfloat16_rn(x);
    __nv_bfloat16 b = __float2bfloat16_rn(y);
    return (uint32_t)__bfloat16_as_ushort(a) | ((uint32_t)__bfloat16_as_ushort(b) << 16);
}

// ---------------- prep codes: zero scratch (block 0) + ||e||^2 + bf16 copy ----------------
__global__ void prep_e_kernel(const float* __restrict__ emb) {
    if (blockIdx.x == 0) {
        for (int i = threadIdx.x; i < K_CODES; i += 256) g_cnt_i[i] = 0;
        if (threadIdx.x == 0) { g_sse = 0.0; g_ortho = 0.0; g_fixcount = 0; }
    }
    int warp = (blockIdx.x * blockDim.x + threadIdx.x) >> 5;
    int lane = threadIdx.x & 31;
    if (warp >= K_CODES) return;
    const float4* p = (const float4*)(emb + (size_t)warp * DIM);
    float4 v0 = p[lane * 2];
    float4 v1 = p[lane * 2 + 1];
    float s = 0.f;
    s = fmaf(v0.x,v0.x,s); s = fmaf(v0.y,v0.y,s); s = fmaf(v0.z,v0.z,s); s = fmaf(v0.w,v0.w,s);
    s = fmaf(v1.x,v1.x,s); s = fmaf(v1.y,v1.y,s); s = fmaf(v1.z,v1.z,s); s = fmaf(v1.w,v1.w,s);
    uint4 hi;
    hi.x = packhi2(v0.x, v0.y);
    hi.y = packhi2(v0.z, v0.w);
    hi.z = packhi2(v1.x, v1.y);
    hi.w = packhi2(v1.z, v1.w);
    ((uint4*)(g_ea + (size_t)warp * DIM))[lane] = hi;
    #pragma unroll
    for (int o = 16; o > 0; o >>= 1) s += __shfl_xor_sync(0xffffffffu, s, o);
    if (lane == 0) g_ee[warp] = s;
}

// ---------------- prep inputs: bf16 + ||x||^2 (warp per row) ----------------
__global__ void prep_x_kernel(const float* __restrict__ inp) {
    size_t base = ((size_t)blockIdx.x * 256 + threadIdx.x) * 8;
    const float4* p = (const float4*)(inp + base);
    float4 v0 = p[0], v1 = p[1];
    float s = 0.f;
    s = fmaf(v0.x,v0.x,s); s = fmaf(v0.y,v0.y,s); s = fmaf(v0.z,v0.z,s); s = fmaf(v0.w,v0.w,s);
    s = fmaf(v1.x,v1.x,s); s = fmaf(v1.y,v1.y,s); s = fmaf(v1.z,v1.z,s); s = fmaf(v1.w,v1.w,s);
    uint4 hi;
    hi.x = packhi2(v0.x, v0.y);
    hi.y = packhi2(v0.z, v0.w);
    hi.z = packhi2(v1.x, v1.y);
    hi.w = packhi2(v1.z, v1.w);
    *(uint4*)(g_xa + base) = hi;
    #pragma unroll
    for (int o = 16; o > 0; o >>= 1) s += __shfl_xor_sync(0xffffffffu, s, o);
    int lane = threadIdx.x & 31;
    if (lane == 0) g_xx[blockIdx.x * 8 + (threadIdx.x >> 5)] = s;
}

// ---------------- HMMA GEMM, 512 threads, X resident in smem, E-only stages ----------------
// smem: XRES[4 kc][128 rows][64 dims] @0 (64K) | E buf0/1 @65536+buf*32768 ([2 kcs][128][64])
// stage s (0..15): n0 = s>>1 (code group of 128), kc2 = s&1 (dims kc2*128..+128)
#define OFB_E  65536
#define E_STRIDE 32768
#define STG_OFF 131072                  // score staging: 128 rows x 272B
#define SMEM_DYN (STG_OFF + 128*272 + 1024)

__device__ __forceinline__ void load_x_res(uint32_t sbase, int R0, int tid) {
    const __nv_bfloat16* xa = g_xa + ((size_t)R0 << 8);
    #pragma unroll
    for (int it = 0; it < 8; it++) {
        int idx = tid + it * 512;           // 0..4095
        int kc  = idx >> 10;                // 64-dim chunk 0..3
        int rem = idx & 1023;
        int r = rem >> 3, kb = rem & 7;
        uint32_t sw = (((uint32_t)kb * 16u) ^ (((uint32_t)r & 7u) * 16u));
        uint32_t d  = sbase + (uint32_t)kc * 16384u + (uint32_t)r * 128u + sw;
        CP_ASYNC16(d, xa + (size_t)r * DIM + kc * 64 + kb * 8);
    }
}

__device__ __forceinline__ void load_e_stage(uint32_t sbase, int st, int tid) {
    int n0 = st >> 1, kc2 = st & 1;
    uint32_t ebase = sbase + OFB_E + (uint32_t)(st & 1) * E_STRIDE;
    const __nv_bfloat16* ea = g_ea + ((size_t)(n0 * 128) << 8) + kc2 * 128;
    #pragma unroll
    for (int it = 0; it < 4; it++) {
        int idx = tid + it * 512;           // 0..2047
        int kcs = idx >> 10;                // sub-chunk 0/1
        int rem = idx & 1023;
        int r = rem >> 3, kb = rem & 7;
        uint32_t sw = (((uint32_t)kb * 16u) ^ (((uint32_t)r & 7u) * 16u));
        uint32_t d  = ebase + (uint32_t)kcs * 16384u + (uint32_t)r * 128u + sw;
        CP_ASYNC16(d, ea + (size_t)r * DIM + kcs * 64 + kb * 8);
    }
}

__global__ void __launch_bounds__(512, 1)
hmma_gemm_kernel()
{
    extern __shared__ __align__(16) char dsm[];
    uint32_t raw   = smem_to_u32(dsm);
    uint32_t sbase = (raw + 1023u) & ~1023u;
    char*    smema = dsm + (sbase - raw);

    const int tid  = threadIdx.x;
    const int lane = tid & 31, wid = tid >> 5;
    const int wr   = wid >> 2, wc = wid & 3;    // wr: 32-row group, wc: 32-code group
    const int R0   = blockIdx.x * 128;
    const int g    = lane >> 2, tig = lane & 3;
    const int q    = lane >> 3, lr  = lane & 7;

    float acc[2][4][4];
    #pragma unroll
    for (int a = 0; a < 2; a++)
        #pragma unroll
        for (int b = 0; b < 4; b++)
            #pragma unroll
            for (int c = 0; c < 4; c++) acc[a][b][c] = 0.f;

    float rs1[4], rs2[4]; int ri[4];
    #pragma unroll
    for (int j = 0; j < 4; j++) { rs1[j] = 3.0e38f; rs2[j] = 3.0e38f; ri[j] = 0x7fffffff; }

    uint32_t* stage_w = (uint32_t*)(smema + STG_OFF);   // row stride = 68 words (272B)

    load_x_res(sbase, R0, tid);
    load_e_stage(sbase, 0, tid);
    CP_COMMIT();                   // group A: X + E0

    for (int s = 0; s < 16; s++) {
        if (s + 1 < 16) load_e_stage(sbase, s + 1, tid);
        CP_COMMIT();
        CP_WAIT1();                // stage s (and X) resident
        __syncthreads();

        const int kc2 = s & 1;
        uint32_t ebase = sbase + OFB_E + (uint32_t)(s & 1) * E_STRIDE;
        #pragma unroll
        for (int kcs = 0; kcs < 2; kcs++) {
            uint32_t xbase = sbase + (uint32_t)(kc2 * 2 + kcs) * 16384u;
            uint32_t ecb   = ebase + (uint32_t)kcs * 16384u;
            #pragma unroll
            for (int ks = 0; ks < 4; ks++) {
                uint32_t axa[8];
                int rowb = wr * 32 + lr + ((q & 1) << 3);
                int kbA  = ks * 2 + (q >> 1);
                uint32_t swA = (((uint32_t)kbA * 16u) ^ ((uint32_t)lr * 16u));
                #pragma unroll
                for (int mf = 0; mf < 2; mf++) {
                    uint32_t ad = xbase + (uint32_t)(rowb + mf * 16) * 128u + swA;
                    LDSM_X4(&axa[mf * 4], ad);
                }
                uint32_t bea[8];
                int kbB = ks * 2 + (q & 1);
                uint32_t swB = (((uint32_t)kbB * 16u) ^ ((uint32_t)lr * 16u));
                #pragma unroll
                for (int np = 0; np < 2; np++) {
                    int code = wc * 32 + np * 16 + lr + ((q >> 1) << 3);
                    uint32_t ed = ecb + (uint32_t)code * 128u + swB;
                    LDSM_X4(&bea[np * 4], ed);
                }
                #pragma unroll
                for (int mf = 0; mf < 2; mf++)
                    #pragma unroll
                    for (int nf = 0; nf < 4; nf++) {
                        int bo = (nf >> 1) * 4 + (nf & 1) * 2;
                        MMA_BF16(acc[mf][nf], &axa[mf * 4], bea[bo], bea[bo + 1]);
                    }
            }
        }

        if (s & 1) {
            int n0 = s >> 1;
            float ee8[8];
            #pragma unroll
            for (int nf = 0; nf < 4; nf++) {
                int code = n0 * 128 + wc * 32 + nf * 8 + tig * 2;
                ee8[nf * 2]     = __ldg(&g_ee[code]);
                ee8[nf * 2 + 1] = __ldg(&g_ee[code + 1]);
            }
            #pragma unroll
            for (int mf = 0; mf < 2; mf++)
                #pragma unroll
                for (int h = 0; h < 2; h++) {
                    int j = mf * 2 + h;
                    int row = wr * 32 + mf * 16 + h * 8 + g;
                    float b1 = 3.0e38f, b2 = 3.0e38f; int bi = 0;
                    #pragma unroll
                    for (int nf = 0; nf < 4; nf++) {
                        int code = n0 * 128 + wc * 32 + nf * 8 + tig * 2;
                        float s0 = fmaf(-2.f, acc[mf][nf][h * 2],     ee8[nf * 2]);
                        float s1 = fmaf(-2.f, acc[mf][nf][h * 2 + 1], ee8[nf * 2 + 1]);
                        __half2 hv = __floats2half2_rn(s0, s1);
                        stage_w[row * 68 + wc * 16 + nf * 4 + tig] = *(uint32_t*)&hv;
                        if (s0 < b1) { b2 = b1; b1 = s0; bi = code; }
                        else if (s0 < b2) b2 = s0;
                        if (s1 < b1) { b2 = b1; b1 = s1; bi = code + 1; }
                        else if (s1 < b2) b2 = s1;
                    }
                    #pragma unroll
                    for (int off = 1; off <= 2; off <<= 1) {
                        float o1 = __shfl_xor_sync(0xffffffffu, b1, off);
                        float o2 = __shfl_xor_sync(0xffffffffu, b2, off);
                        int   oi = __shfl_xor_sync(0xffffffffu, bi, off);
                        if (o1 < b1) { b2 = fminf(b1, o2); b1 = o1; bi = oi; }
                        else         { b2 = fminf(b2, o1); }
                    }
                    if (b1 < rs1[j]) { rs2[j] = fminf(rs1[j], b2); rs1[j] = b1; ri[j] = bi; }
                    else             { rs2[j] = fminf(rs2[j], b1); }
                }
            __syncthreads();
            // coalesced streaming copy staging -> g_sc[row][n0*128 .. +128)
            #pragma unroll
            for (int it = 0; it < 4; it++) {
                int idx = tid + it * 512;          // 0..2047
                int row = idx >> 4, seg = idx & 15;
                uint4 v = *(const uint4*)(smema + STG_OFF + row * 272 + seg * 16);
                char* gp = (char*)(g_sc + (size_t)(R0 + row) * K_CODES + n0 * 128) + seg * 16;
                STG_CS_V4(gp, v);
            }
            #pragma unroll
            for (int a = 0; a < 2; a++)
                #pragma unroll
                for (int b = 0; b < 4; b++)
                    #pragma unroll
                    for (int c = 0; c < 4; c++) acc[a][b][c] = 0.f;
        }
        __syncthreads();
    }

    // final cross-warp merge (alias XRES smem; all MMA work done)
    float* fs1 = (float*)smema;
    float* fs2 = (float*)(smema + 2048);
    int*   fi1 = (int*)  (smema + 4096);
    #pragma unroll
    for (int mf = 0; mf < 2; mf++)
        #pragma unroll
        for (int h = 0; h < 2; h++) {
            int j = mf * 2 + h;
            int row = wr * 32 + mf * 16 + h * 8 + g;
            fs1[row * 4 + wc] = rs1[j];
            fs2[row * 4 + wc] = rs2[j];
            fi1[row * 4 + wc] = ri[j];
        }
    __syncthreads();
    if (tid < 128) {
        float b1 = 3.0e38f, b2 = 3.0e38f; int bi = 0;
        #pragma unroll
        for (int w = 0; w < 4; w++) {
            float o1 = fs1[tid * 4 + w], o2 = fs2[tid * 4 + w];
            int   oi = fi1[tid * 4 + w];
            if (o1 < b1) { b2 = fminf(b1, o2); b1 = o1; bi = oi; }
            else         { b2 = fminf(b2, o1); }
        }
        g_idx[R0 + tid] = bi;
        atomicAdd(&g_cnt_i[bi], 1);                 // tentative histogram
        if (b2 - b1 < TAU_F) {
            int p = atomicAdd(&g_fixcount, 1);
            if (p < FIX_CAP) g_fixrows[p] = R0 + tid;
        }
    }
}

// ---------------- candidate rescore: warp per flagged row, exact fp32 on few codes ----------------
__global__ void __launch_bounds__(256)
rescore2_kernel(const float* __restrict__ inp, const float* __restrict__ emb)
{
    int n = g_fixcount; if (n > FIX_CAP) n = FIX_CAP;
    int gw   = (blockIdx.x * 256 + threadIdx.x) >> 5;
    int lane = threadIdx.x & 31;
    const int NW = (1024 * 256) >> 5;

    for (int fi = gw; fi < n; fi += NW) {
        int row = g_fixrows[fi];
        const __half* sc = g_sc + (size_t)row * K_CODES;

        float m = 3.0e38f;
        #pragma unroll
        for (int it = 0; it < 4; it++) {
            uint4 v = ((const uint4*)sc)[it * 32 + lane];
            const __half2* h = (const __half2*)&v;
            #pragma unroll
            for (int j = 0; j < 4; j++) {
                float2 f = __half22float2(h[j]);
                m = fminf(m, fminf(f.x, f.y));
            }
        }
        #pragma unroll
        for (int o = 16; o > 0; o >>= 1) m = fminf(m, __shfl_xor_sync(0xffffffffu, m, o));
        float thr = m + CAND_W;

        const float4* xr = (const float4*)(inp + (size_t)row * DIM);
        float4 xa = xr[lane * 2], xb = xr[lane * 2 + 1];
        float xx = g_xx[row];

        float bd = 3.0e38f; int bi = 0x7fffffff;
        for (int ci = 0; ci < 32; ci++) {
            float sv = __half2float(sc[ci * 32 + lane]);
            unsigned mask = __ballot_sync(0xffffffffu, sv <= thr);
            while (mask) {
                int b_ = __ffs(mask) - 1; mask &= mask - 1;
                int cc = ci * 32 + b_;
                const float4* er = (const float4*)(emb + (size_t)cc * DIM);
                float4 e0 = er[lane * 2], e1 = er[lane * 2 + 1];
                float d = 0.f;
                d = fmaf(e0.x, xa.x, d); d = fmaf(e0.y, xa.y, d);
                d = fmaf(e0.z, xa.z, d); d = fmaf(e0.w, xa.w, d);
                d = fmaf(e1.x, xb.x, d); d = fmaf(e1.y, xb.y, d);
                d = fmaf(e1.z, xb.z, d); d = fmaf(e1.w, xb.w, d);
                #pragma unroll
                for (int o = 16; o > 0; o >>= 1) d += __shfl_xor_sync(0xffffffffu, d, o);
                float dist = (xx + g_ee[cc]) - 2.0f * d;
                if (dist < bd || (dist == bd && cc < bi)) { bd = dist; bi = cc; }
            }
        }
        if (lane == 0) {
            int old = g_idx[row];
            if (bi != old) {
                g_idx[row] = bi;
                atomicAdd(&g_cnt_i[old], -1);
                atomicAdd(&g_cnt_i[bi], 1);
            }
        }
    }
}

// ---------------- offsets ----------------
__global__ void offsets_kernel() {
    __shared__ int tmp[2][1024];
    int t = threadIdx.x;
    int v = g_cnt_i[t];
    g_counts[t] = (float)v;
    tmp[0][t] = v;
    __syncthreads();
    int src = 0;
    #pragma unroll
    for (int d = 1; d < 1024; d <<= 1) {
        int nv = tmp[src][t] + (t >= d ? tmp[src][t - d] : 0);
        tmp[src ^ 1][t] = nv;
        src ^= 1;
        __syncthreads();
    }
    int off = tmp[src][t] - v;   // exclusive
    g_off[t] = off;
    g_cursor[t] = off;
}

// ---------------- scatter (side stream, overlapped with epilogue) ----------------
__global__ void scatter_kernel() {
    int i = blockIdx.x * blockDim.x + threadIdx.x;
    int k = g_idx[i];
    int pos = atomicAdd(&g_cursor[k], 1);
    g_rowlist[pos] = i;
}

// ---------------- segment-sum ----------------
__global__ void __launch_bounds__(256)
segsum_kernel(const float* __restrict__ inp) {
    int k = blockIdx.x, t = threadIdx.x;
    int beg = g_off[k], cnt = g_cnt_i[k];
    float s = 0.f;
    int j = 0;
    for (; j + 4 <= cnt; j += 4) {
        int r0 = g_rowlist[beg + j],     r1 = g_rowlist[beg + j + 1];
        int r2 = g_rowlist[beg + j + 2], r3 = g_rowlist[beg + j + 3];
        float v0 = inp[(size_t)r0 * DIM + t];
        float v1 = inp[(size_t)r1 * DIM + t];
        float v2 = inp[(size_t)r2 * DIM + t];
        float v3 = inp[(size_t)r3 * DIM + t];
        s += v0; s += v1; s += v2; s += v3;
    }
    for (; j < cnt; j++) s += inp[(size_t)g_rowlist[beg + j] * DIM + t];
    g_embsum[k * DIM + t] = s;
}

// ---------------- epilogue: gather + Q/idx output + MSE ----------------
__global__ void __launch_bounds__(256)
epilogue_kernel(const float* __restrict__ inp, const float* __restrict__ emb,
                float* __restrict__ out)
{
    __shared__ int besti[128];
    __shared__ double dred[256];
    const int tid = threadIdx.x;
    const int R0  = blockIdx.x * 128;
    if (tid < 128) {
        int v = g_idx[R0 + tid];
        besti[tid] = v;
        out[OFF_IDX + R0 + tid] = (float)v;
    }
    __syncthreads();

    float sse = 0.f;
    const float4* inp4 = (const float4*)inp;
    const float4* emb4 = (const float4*)emb;
    float4* out4 = (float4*)(out + OFF_Q);
    #pragma unroll 4
    for (int j = 0; j < 32; j++) {
        int e4  = tid + j * 256;
        int r   = e4 >> 6;
        int c4  = e4 & 63;
        int idx = besti[r];
        float4 ev = emb4[idx * 64 + c4];
        float4 xv = inp4[(size_t)(R0 + r) * 64 + c4];
        float4 qv;
        qv.x = xv.x + (ev.x - xv.x);
        qv.y = xv.y + (ev.y - xv.y);
        qv.z = xv.z + (ev.z - xv.z);
        qv.w = xv.w + (ev.w - xv.w);
        out4[(size_t)(R0 + r) * 64 + c4] = qv;
        float d0 = ev.x - xv.x, d1 = ev.y - xv.y, d2 = ev.z - xv.z, d3 = ev.w - xv.w;
        sse = fmaf(d0, d0, sse); sse = fmaf(d1, d1, sse);
        sse = fmaf(d2, d2, sse); sse = fmaf(d3, d3, sse);
    }
    dred[tid] = (double)sse;
    __syncthreads();
    #pragma unroll
    for (int s = 128; s > 0; s >>= 1) {
        if (tid < s) dred[tid] += dred[tid + s];
        __syncthreads();
    }
    if (tid == 0) atomicAdd(&g_sse, dred[0]);
}

// ---------------- ortho via ||E^T E||_F^2 ----------------
__global__ void gram_kernel(const float* __restrict__ emb) {
    __shared__ float sA[64][16];
    __shared__ float sB[64][16];
    __shared__ double sred[256];
    int tx = threadIdx.x & 15;
    int ty = threadIdx.x >> 4;
    int a0 = blockIdx.y * 16;
    int b0 = blockIdx.x * 16;
    float acc = 0.f;
    for (int k0 = 0; k0 < K_CODES; k0 += 64) {
        __syncthreads();
        #pragma unroll
        for (int i = 0; i < 4; i++) {
            int e = threadIdx.x + i * 256;
            int kr = e >> 4, c = e & 15;
            sA[kr][c] = emb[(size_t)(k0 + kr) * DIM + a0 + c];
            sB[kr][c] = emb[(size_t)(k0 + kr) * DIM + b0 + c];
        }
        __syncthreads();
        #pragma unroll 8
        for (int kk = 0; kk < 64; kk++)
            acc = fmaf(sA[kk][ty], sB[kk][tx], acc);
    }
    sred[threadIdx.x] = (double)acc * (double)acc;
    __syncthreads();
    #pragma unroll
    for (int s = 128; s > 0; s >>= 1) {
        if (threadIdx.x < s) sred[threadIdx.x] += sred[threadIdx.x + s];
        __syncthreads();
    }
    if (threadIdx.x == 0) atomicAdd(&g_ortho, sred[0]);
}

// ---------------- EMA finalize ----------------
__global__ void ema_a_kernel(const float* __restrict__ ema_cs, float* __restrict__ out) {
    __shared__ double sred[1024];
    int k = threadIdx.x;
    float ncs = 0.99f * ema_cs[k] + 0.01f * g_counts[k];
    out[OFF_NCS + k] = ncs;
    g_ncs[k] = ncs;
    sred[k] = (double)ncs;
    __syncthreads();
    #pragma unroll
    for (int s = 512; s > 0; s >>= 1) {
        if (k < s) sred[k] += sred[k + s];
        __syncthreads();
    }
    if (k == 0) g_ntotal = (float)sred[0] + EPS_F;
}
__global__ void ema_b_kernel(const float* __restrict__ ema_avg, float* __restrict__ out) {
    int k = blockIdx.x;
    int d = threadIdx.x;
    int i = k * DIM + d;
    float navg = 0.99f * ema_avg[i] + 0.01f * g_embsum[i];
    out[OFF_NAVG + i] = navg;
    float cs = (g_ncs[k] + EPS_F) / g_ntotal;
    out[OFF_NEWEMB + i] = navg / cs;
}

// ---------------- loss ----------------
__global__ void loss_fin_kernel(float* __restrict__ out) {
    __shared__ double sred[256];
    double s = 0.0;
    for (int k = threadIdx.x; k < K_CODES; k += 256) {
        double e = (double)g_ee[k];
        s += e * e;
    }
    sred[threadIdx.x] = s;
    __syncthreads();
    #pragma unroll
    for (int t = 128; t > 0; t >>= 1) {
        if (threadIdx.x < t) sred[threadIdx.x] += sred[threadIdx.x + t];
        __syncthreads();
    }
    if (threadIdx.x == 0) {
        double o2 = g_ortho - sred[0];
        if (o2 < 0.0) o2 = 0.0;
        float ortho = sqrtf((float)o2);
        float m = (float)(g_sse / (double)((size_t)N_ROWS * DIM));
        out[OFF_LOSS] = (m + 0.25f * m) + 0.09f * ortho;
    }
}

// ---------------- launch ----------------
extern "C" void kernel_launch(void* const* d_in, const int* in_sizes, int n_in,
                              void* d_out, int out_size)
{
    const float* inp     = (const float*)d_in[0];
    const float* emb     = (const float*)d_in[1];
    const float* ema_cs  = (const float*)d_in[2];
    const float* ema_avg = (const float*)d_in[3];
    float* out = (float*)d_out;

    static int inited = 0;
    static cudaStream_t s2;
    static cudaEvent_t ev_root, ev_pe, ev_side, ev_off, ev_seg;
    if (!inited) {
        cudaFuncSetAttribute(hmma_gemm_kernel,
                             cudaFuncAttributeMaxDynamicSharedMemorySize, SMEM_DYN);
        cudaStreamCreateWithFlags(&s2, cudaStreamNonBlocking);
        cudaEventCreateWithFlags(&ev_root, cudaEventDisableTiming);
        cudaEventCreateWithFlags(&ev_pe,   cudaEventDisableTiming);
        cudaEventCreateWithFlags(&ev_side, cudaEventDisableTiming);
        cudaEventCreateWithFlags(&ev_off,  cudaEventDisableTiming);
        cudaEventCreateWithFlags(&ev_seg,  cudaEventDisableTiming);
        inited = 1;
    }

    // fork side stream: prep_e + gram (independent of main chain until gemm/loss)
    cudaEventRecord(ev_root, 0);
    cudaStreamWaitEvent(s2, ev_root, 0);
    prep_e_kernel<<<K_CODES / 8, 256, 0, s2>>>(emb);
    cudaEventRecord(ev_pe, s2);
    gram_kernel<<<dim3(16, 16), 256, 0, s2>>>(emb);
    cudaEventRecord(ev_side, s2);

    prep_x_kernel<<<(N_ROWS * DIM) / (256 * 8), 256>>>(inp);
    cudaStreamWaitEvent(0, ev_pe, 0);          // gemm needs g_ea/g_ee/g_cnt_i
    hmma_gemm_kernel<<<N_ROWS / 128, 512, SMEM_DYN>>>();
    rescore2_kernel<<<1024, 256>>>(inp, emb);
    offsets_kernel<<<1, 1024>>>();
    cudaEventRecord(ev_off, 0);

    // side stream: scatter + segsum overlapped with main epilogue
    cudaStreamWaitEvent(s2, ev_off, 0);
    scatter_kernel<<<N_ROWS / 1024, 1024, 0, s2>>>();
    segsum_kernel<<<K_CODES, 256, 0, s2>>>(inp);
    cudaEventRecord(ev_seg, s2);

    epilogue_kernel<<<N_ROWS / 128, 256>>>(inp, emb, out);
    ema_a_kernel<<<1, 1024>>>(ema_cs, out);
    cudaStreamWaitEvent(0, ev_seg, 0);         // ema_b needs g_embsum
    ema_b_kernel<<<K_CODES, 256>>>(ema_avg, out);
    cudaStreamWaitEvent(0, ev_side, 0);        // loss needs g_ortho
    loss_fin_kernel<<<1, 256>>>(out);
}

// round 14
// speedup vs baseline: 1.0207x; 1.0078x over previous
#include <cuda_runtime.h>
#include <cuda_bf16.h>
#include <cuda_fp16.h>
#include <math.h>
#include <stdint.h>

// ---------------- problem constants ----------------
#define N_ROWS   131072
#define DIM      256
#define K_CODES  1024
#define EPS_F    1e-5f
#define TAU_F    3.5e-4f
#define CAND_W   6.0e-4f
#define FIX_CAP  131072

// output layout (float32 elements), reference return order
#define OFF_Q       0
#define OFF_LOSS    33554432
#define OFF_IDX     33554433
#define OFF_NEWEMB  33685505
#define OFF_NCS     33947649
#define OFF_NAVG    33948673

// ---------------- device scratch ----------------
__device__ float  g_xx[N_ROWS];
__device__ float  g_smin[N_ROWS];
__device__ float  g_ee[K_CODES];
__device__ float  g_counts[K_CODES];
__device__ float  g_embsum[K_CODES*DIM];
__device__ float  g_ncs[K_CODES];
__device__ float  g_ntotal;
__device__ double g_sse;
__device__ double g_ortho;
__device__ int    g_fixcount;
__device__ int    g_fixrows[FIX_CAP];
__device__ int    g_idx[N_ROWS];
__device__ int    g_cnt_i[K_CODES];
__device__ int    g_off[K_CODES];
__device__ int    g_cursor[K_CODES];
__device__ int    g_rowlist[N_ROWS];
__device__ __nv_bfloat16 g_ea[K_CODES*DIM];
__device__ __nv_bfloat16 g_xa[(size_t)N_ROWS*DIM];
__device__ __half g_sc[(size_t)N_ROWS*K_CODES];   // screened scores, fp16

// ---------------- PTX helpers (baseline sm_80+ ISA only) ----------------
__device__ __forceinline__ uint32_t smem_to_u32(const void* p) {
    uint32_t a;
    asm("{ .reg .u64 t; cvta.to.shared.u64 t, %1; cvt.u32.u64 %0, t; }" : "=r"(a) : "l"(p));
    return a;
}
#define CP_ASYNC16(dst, src) \
    asm volatile("cp.async.cg.shared.global [%0], [%1], 16;" :: "r"(dst), "l"(src))
#define CP_COMMIT() asm volatile("cp.async.commit_group;" ::: "memory")
#define CP_WAIT1()  asm volatile("cp.async.wait_group 1;" ::: "memory")

#define LDSM_X4(r, addr) \
    asm volatile("ldmatrix.sync.aligned.m8n8.x4.shared.b16 {%0,%1,%2,%3}, [%4];" \
        : "=r"((r)[0]), "=r"((r)[1]), "=r"((r)[2]), "=r"((r)[3]) : "r"(addr))

#define MMA_BF16(c, a, b0, b1) \
    asm volatile("mma.sync.aligned.m16n8k16.row.col.f32.bf16.bf16.f32 " \
        "{%0,%1,%2,%3},{%4,%5,%6,%7},{%8,%9},{%0,%1,%2,%3};" \
        : "+f"((c)[0]), "+f"((c)[1]), "+f"((c)[2]), "+f"((c)[3]) \
        : "r"((a)[0]), "r"((a)[1]), "r"((a)[2]), "r"((a)[3]), "r"(b0), "r"(b1))

__device__ __forceinline__ uint32_t packhi2(float x, float y) {
    __nv_bfloat16 a = __float2bfloat16_rn(x);
    __nv_bfloat16 b = __float2bfloat16_rn(y);
    return (uint32_t)__bfloat16_as_ushort(a) | ((uint32_t)__bfloat16_as_ushort(b) << 16);
}

// ---------------- prep codes: zero scratch (block 0) + ||e||^2 + bf16 copy ----------------
__global__ void prep_e_kernel(const float* __restrict__ emb) {
    if (blockIdx.x == 0) {
        for (int i = threadIdx.x; i < K_CODES; i += 256) g_cnt_i[i] = 0;
        if (threadIdx.x == 0) { g_sse = 0.0; g_ortho = 0.0; g_fixcount = 0; }
    }
    int warp = (blockIdx.x * blockDim.x + threadIdx.x) >> 5;
    int lane = threadIdx.x & 31;
    if (warp >= K_CODES) return;
    const float4* p = (const float4*)(emb + (size_t)warp * DIM);
    float4 v0 = p[lane * 2];
    float4 v1 = p[lane * 2 + 1];
    float s = 0.f;
    s = fmaf(v0.x,v0.x,s); s = fmaf(v0.y,v0.y,s); s = fmaf(v0.z,v0.z,s); s = fmaf(v0.w,v0.w,s);
    s = fmaf(v1.x,v1.x,s); s = fmaf(v1.y,v1.y,s); s = fmaf(v1.z,v1.z,s); s = fmaf(v1.w,v1.w,s);
    uint4 hi;
    hi.x = packhi2(v0.x, v0.y);
    hi.y = packhi2(v0.z, v0.w);
    hi.z = packhi2(v1.x, v1.y);
    hi.w = packhi2(v1.z, v1.w);
    ((uint4*)(g_ea + (size_t)warp * DIM))[lane] = hi;
    #pragma unroll
    for (int o = 16; o > 0; o >>= 1) s += __shfl_xor_sync(0xffffffffu, s, o);
    if (lane == 0) g_ee[warp] = s;
}

// ---------------- prep inputs: bf16 + ||x||^2 (warp per row) ----------------
__global__ void prep_x_kernel(const float* __restrict__ inp) {
    size_t base = ((size_t)blockIdx.x * 256 + threadIdx.x) * 8;
    const float4* p = (const float4*)(inp + base);
    float4 v0 = p[0], v1 = p[1];
    float s = 0.f;
    s = fmaf(v0.x,v0.x,s); s = fmaf(v0.y,v0.y,s); s = fmaf(v0.z,v0.z,s); s = fmaf(v0.w,v0.w,s);
    s = fmaf(v1.x,v1.x,s); s = fmaf(v1.y,v1.y,s); s = fmaf(v1.z,v1.z,s); s = fmaf(v1.w,v1.w,s);
    uint4 hi;
    hi.x = packhi2(v0.x, v0.y);
    hi.y = packhi2(v0.z, v0.w);
    hi.z = packhi2(v1.x, v1.y);
    hi.w = packhi2(v1.z, v1.w);
    *(uint4*)(g_xa + base) = hi;
    #pragma unroll
    for (int o = 16; o > 0; o >>= 1) s += __shfl_xor_sync(0xffffffffu, s, o);
    int lane = threadIdx.x & 31;
    if (lane == 0) g_xx[blockIdx.x * 8 + (threadIdx.x >> 5)] = s;
}

// ---------------- HMMA GEMM, 512 threads, X resident in smem, E-only stages ----------------
// smem: XRES[4 kc][128 rows][64 dims] @0 (64K) | E buf0/1 @65536+buf*32768 ([2 kcs][128][64])
// stage s (0..15): n0 = s>>1 (code group of 128), kc2 = s&1 (dims kc2*128..+128)
#define OFB_E  65536
#define E_STRIDE 32768
#define STG_OFF 131072                  // score staging: 128 rows x 272B
#define SMEM_DYN (STG_OFF + 128*272 + 1024)

__device__ __forceinline__ void load_x_res(uint32_t sbase, int R0, int tid) {
    const __nv_bfloat16* xa = g_xa + ((size_t)R0 << 8);
    #pragma unroll
    for (int it = 0; it < 8; it++) {
        int idx = tid + it * 512;           // 0..4095
        int kc  = idx >> 10;                // 64-dim chunk 0..3
        int rem = idx & 1023;
        int r = rem >> 3, kb = rem & 7;
        uint32_t sw = (((uint32_t)kb * 16u) ^ (((uint32_t)r & 7u) * 16u));
        uint32_t d  = sbase + (uint32_t)kc * 16384u + (uint32_t)r * 128u + sw;
        CP_ASYNC16(d, xa + (size_t)r * DIM + kc * 64 + kb * 8);
    }
}

__device__ __forceinline__ void load_e_stage(uint32_t sbase, int st, int tid) {
    int n0 = st >> 1, kc2 = st & 1;
    uint32_t ebase = sbase + OFB_E + (uint32_t)(st & 1) * E_STRIDE;
    const __nv_bfloat16* ea = g_ea + ((size_t)(n0 * 128) << 8) + kc2 * 128;
    #pragma unroll
    for (int it = 0; it < 4; it++) {
        int idx = tid + it * 512;           // 0..2047
        int kcs = idx >> 10;                // sub-chunk 0/1
        int rem = idx & 1023;
        int r = rem >> 3, kb = rem & 7;
        uint32_t sw = (((uint32_t)kb * 16u) ^ (((uint32_t)r & 7u) * 16u));
        uint32_t d  = ebase + (uint32_t)kcs * 16384u + (uint32_t)r * 128u + sw;
        CP_ASYNC16(d, ea + (size_t)r * DIM + kcs * 64 + kb * 8);
    }
}

__global__ void __launch_bounds__(512, 1)
hmma_gemm_kernel()
{
    extern __shared__ __align__(16) char dsm[];
    uint32_t raw   = smem_to_u32(dsm);
    uint32_t sbase = (raw + 1023u) & ~1023u;
    char*    smema = dsm + (sbase - raw);

    const int tid  = threadIdx.x;
    const int lane = tid & 31, wid = tid >> 5;
    const int wr   = wid >> 2, wc = wid & 3;    // wr: 32-row group, wc: 32-code group
    const int R0   = blockIdx.x * 128;
    const int g    = lane >> 2, tig = lane & 3;
    const int q    = lane >> 3, lr  = lane & 7;

    float acc[2][4][4];
    #pragma unroll
    for (int a = 0; a < 2; a++)
        #pragma unroll
        for (int b = 0; b < 4; b++)
            #pragma unroll
            for (int c = 0; c < 4; c++) acc[a][b][c] = 0.f;

    float rs1[4], rs2[4]; int ri[4];
    #pragma unroll
    for (int j = 0; j < 4; j++) { rs1[j] = 3.0e38f; rs2[j] = 3.0e38f; ri[j] = 0x7fffffff; }

    uint32_t* stage_w = (uint32_t*)(smema + STG_OFF);   // row stride = 68 words (272B)

    load_x_res(sbase, R0, tid);
    load_e_stage(sbase, 0, tid);
    CP_COMMIT();                   // group A: X + E0

    for (int s = 0; s < 16; s++) {
        if (s + 1 < 16) load_e_stage(sbase, s + 1, tid);
        CP_COMMIT();
        CP_WAIT1();                // stage s (and X) resident
        __syncthreads();

        const int kc2 = s & 1;
        uint32_t ebase = sbase + OFB_E + (uint32_t)(s & 1) * E_STRIDE;
        #pragma unroll
        for (int kcs = 0; kcs < 2; kcs++) {
            uint32_t xbase = sbase + (uint32_t)(kc2 * 2 + kcs) * 16384u;
            uint32_t ecb   = ebase + (uint32_t)kcs * 16384u;
            #pragma unroll
            for (int ks = 0; ks < 4; ks++) {
                uint32_t axa[8];
                int rowb = wr * 32 + lr + ((q & 1) << 3);
                int kbA  = ks * 2 + (q >> 1);
                uint32_t swA = (((uint32_t)kbA * 16u) ^ ((uint32_t)lr * 16u));
                #pragma unroll
                for (int mf = 0; mf < 2; mf++) {
                    uint32_t ad = xbase + (uint32_t)(rowb + mf * 16) * 128u + swA;
                    LDSM_X4(&axa[mf * 4], ad);
                }
                uint32_t bea[8];
                int kbB = ks * 2 + (q & 1);
                uint32_t swB = (((uint32_t)kbB * 16u) ^ ((uint32_t)lr * 16u));
                #pragma unroll
                for (int np = 0; np < 2; np++) {
                    int code = wc * 32 + np * 16 + lr + ((q >> 1) << 3);
                    uint32_t ed = ecb + (uint32_t)code * 128u + swB;
                    LDSM_X4(&bea[np * 4], ed);
                }
                #pragma unroll
                for (int mf = 0; mf < 2; mf++)
                    #pragma unroll
                    for (int nf = 0; nf < 4; nf++) {
                        int bo = (nf >> 1) * 4 + (nf & 1) * 2;
                        MMA_BF16(acc[mf][nf], &axa[mf * 4], bea[bo], bea[bo + 1]);
                    }
            }
        }

        if (s & 1) {
            int n0 = s >> 1;
            float ee8[8];
            #pragma unroll
            for (int nf = 0; nf < 4; nf++) {
                int code = n0 * 128 + wc * 32 + nf * 8 + tig * 2;
                ee8[nf * 2]     = __ldg(&g_ee[code]);
                ee8[nf * 2 + 1] = __ldg(&g_ee[code + 1]);
            }
            #pragma unroll
            for (int mf = 0; mf < 2; mf++)
                #pragma unroll
                for (int h = 0; h < 2; h++) {
                    int j = mf * 2 + h;
                    int row = wr * 32 + mf * 16 + h * 8 + g;
                    float b1 = 3.0e38f, b2 = 3.0e38f; int bi = 0;
                    #pragma unroll
                    for (int nf = 0; nf < 4; nf++) {
                        int code = n0 * 128 + wc * 32 + nf * 8 + tig * 2;
                        float s0 = fmaf(-2.f, acc[mf][nf][h * 2],     ee8[nf * 2]);
                        float s1 = fmaf(-2.f, acc[mf][nf][h * 2 + 1], ee8[nf * 2 + 1]);
                        __half2 hv = __floats2half2_rn(s0, s1);
                        stage_w[row * 68 + wc * 16 + nf * 4 + tig] = *(uint32_t*)&hv;
                        if (s0 < b1) { b2 = b1; b1 = s0; bi = code; }
                        else if (s0 < b2) b2 = s0;
                        if (s1 < b1) { b2 = b1; b1 = s1; bi = code + 1; }
                        else if (s1 < b2) b2 = s1;
                    }
                    #pragma unroll
                    for (int off = 1; off <= 2; off <<= 1) {
                        float o1 = __shfl_xor_sync(0xffffffffu, b1, off);
                        float o2 = __shfl_xor_sync(0xffffffffu, b2, off);
                        int   oi = __shfl_xor_sync(0xffffffffu, bi, off);
                        if (o1 < b1) { b2 = fminf(b1, o2); b1 = o1; bi = oi; }
                        else         { b2 = fminf(b2, o1); }
                    }
                    if (b1 < rs1[j]) { rs2[j] = fminf(rs1[j], b2); rs1[j] = b1; ri[j] = bi; }
                    else             { rs2[j] = fminf(rs2[j], b1); }
                }
            __syncthreads();
            // coalesced copy staging -> g_sc[row][n0*128 .. +128)
            #pragma unroll
            for (int it = 0; it < 4; it++) {
                int idx = tid + it * 512;          // 0..2047
                int row = idx >> 4, seg = idx & 15;
                uint4 v = *(const uint4*)(smema + STG_OFF + row * 272 + seg * 16);
                *(uint4*)((char*)(g_sc + (size_t)(R0 + row) * K_CODES + n0 * 128) + seg * 16) = v;
            }
            #pragma unroll
            for (int a = 0; a < 2; a++)
                #pragma unroll
                for (int b = 0; b < 4; b++)
                    #pragma unroll
                    for (int c = 0; c < 4; c++) acc[a][b][c] = 0.f;
        }
        __syncthreads();
    }

    // final cross-warp merge (alias XRES smem; all MMA work done)
    float* fs1 = (float*)smema;
    float* fs2 = (float*)(smema + 2048);
    int*   fi1 = (int*)  (smema + 4096);
    #pragma unroll
    for (int mf = 0; mf < 2; mf++)
        #pragma unroll
        for (int h = 0; h < 2; h++) {
            int j = mf * 2 + h;
            int row = wr * 32 + mf * 16 + h * 8 + g;
            fs1[row * 4 + wc] = rs1[j];
            fs2[row * 4 + wc] = rs2[j];
            fi1[row * 4 + wc] = ri[j];
        }
    __syncthreads();
    if (tid < 128) {
        float b1 = 3.0e38f, b2 = 3.0e38f; int bi = 0;
        #pragma unroll
        for (int w = 0; w < 4; w++) {
            float o1 = fs1[tid * 4 + w], o2 = fs2[tid * 4 + w];
            int   oi = fi1[tid * 4 + w];
            if (o1 < b1) { b2 = fminf(b1, o2); b1 = o1; bi = oi; }
            else         { b2 = fminf(b2, o1); }
        }
        g_idx[R0 + tid] = bi;
        g_smin[R0 + tid] = b1;                      // screened min for rescore threshold
        atomicAdd(&g_cnt_i[bi], 1);                 // tentative histogram
        if (b2 - b1 < TAU_F) {
            int p = atomicAdd(&g_fixcount, 1);
            if (p < FIX_CAP) g_fixrows[p] = R0 + tid;
        }
    }
}

// ---------------- candidate rescore: warp per flagged row (uses g_smin, no min-scan) ----------------
__global__ void __launch_bounds__(256)
rescore2_kernel(const float* __restrict__ inp, const float* __restrict__ emb)
{
    int n = g_fixcount; if (n > FIX_CAP) n = FIX_CAP;
    int gw   = (blockIdx.x * 256 + threadIdx.x) >> 5;
    int lane = threadIdx.x & 31;
    const int NW = (1024 * 256) >> 5;

    for (int fi = gw; fi < n; fi += NW) {
        int row = g_fixrows[fi];
        const __half* sc = g_sc + (size_t)row * K_CODES;
        float thr = g_smin[row] + CAND_W;

        const float4* xr = (const float4*)(inp + (size_t)row * DIM);
        float4 xa = xr[lane * 2], xb = xr[lane * 2 + 1];
        float xx = g_xx[row];

        float bd = 3.0e38f; int bi = 0x7fffffff;
        for (int ci = 0; ci < 32; ci++) {
            float sv = __half2float(sc[ci * 32 + lane]);
            unsigned mask = __ballot_sync(0xffffffffu, sv <= thr);
            while (mask) {
                int b_ = __ffs(mask) - 1; mask &= mask - 1;
                int cc = ci * 32 + b_;
                const float4* er = (const float4*)(emb + (size_t)cc * DIM);
                float4 e0 = er[lane * 2], e1 = er[lane * 2 + 1];
                float d = 0.f;
                d = fmaf(e0.x, xa.x, d); d = fmaf(e0.y, xa.y, d);
                d = fmaf(e0.z, xa.z, d); d = fmaf(e0.w, xa.w, d);
                d = fmaf(e1.x, xb.x, d); d = fmaf(e1.y, xb.y, d);
                d = fmaf(e1.z, xb.z, d); d = fmaf(e1.w, xb.w, d);
                #pragma unroll
                for (int o = 16; o > 0; o >>= 1) d += __shfl_xor_sync(0xffffffffu, d, o);
                float dist = (xx + g_ee[cc]) - 2.0f * d;
                if (dist < bd || (dist == bd && cc < bi)) { bd = dist; bi = cc; }
            }
        }
        if (lane == 0) {
            int old = g_idx[row];
            if (bi != old) {
                g_idx[row] = bi;
                atomicAdd(&g_cnt_i[old], -1);
                atomicAdd(&g_cnt_i[bi], 1);
            }
        }
    }
}

// ---------------- offsets + ema_a (fused) ----------------
__global__ void offsets_kernel(const float* __restrict__ ema_cs, float* __restrict__ out) {
    __shared__ int tmp[2][1024];
    __shared__ double sred[1024];
    int t = threadIdx.x;
    int v = g_cnt_i[t];
    g_counts[t] = (float)v;
    tmp[0][t] = v;
    __syncthreads();
    int src = 0;
    #pragma unroll
    for (int d = 1; d < 1024; d <<= 1) {
        int nv = tmp[src][t] + (t >= d ? tmp[src][t - d] : 0);
        tmp[src ^ 1][t] = nv;
        src ^= 1;
        __syncthreads();
    }
    int off = tmp[src][t] - v;   // exclusive
    g_off[t] = off;
    g_cursor[t] = off;

    // ---- fused ema_a ----
    float ncs = 0.99f * ema_cs[t] + 0.01f * (float)v;
    out[OFF_NCS + t] = ncs;
    g_ncs[t] = ncs;
    sred[t] = (double)ncs;
    __syncthreads();
    #pragma unroll
    for (int s = 512; s > 0; s >>= 1) {
        if (t < s) sred[t] += sred[t + s];
        __syncthreads();
    }
    if (t == 0) g_ntotal = (float)sred[0] + EPS_F;
}

// ---------------- epilogue: gather + Q/idx output + MSE + rowlist scatter ----------------
__global__ void __launch_bounds__(256)
epilogue_kernel(const float* __restrict__ inp, const float* __restrict__ emb,
                float* __restrict__ out)
{
    __shared__ int besti[128];
    __shared__ double dred[256];
    const int tid = threadIdx.x;
    const int R0  = blockIdx.x * 128;
    if (tid < 128) {
        int v = g_idx[R0 + tid];
        besti[tid] = v;
        out[OFF_IDX + R0 + tid] = (float)v;
        int pos = atomicAdd(&g_cursor[v], 1);      // fused scatter
        g_rowlist[pos] = R0 + tid;
    }
    __syncthreads();

    float sse = 0.f;
    const float4* inp4 = (const float4*)inp;
    const float4* emb4 = (const float4*)emb;
    float4* out4 = (float4*)(out + OFF_Q);
    #pragma unroll 4
    for (int j = 0; j < 32; j++) {
        int e4  = tid + j * 256;
        int r   = e4 >> 6;
        int c4  = e4 & 63;
        int idx = besti[r];
        float4 ev = emb4[idx * 64 + c4];
        float4 xv = inp4[(size_t)(R0 + r) * 64 + c4];
        float4 qv;
        qv.x = xv.x + (ev.x - xv.x);
        qv.y = xv.y + (ev.y - xv.y);
        qv.z = xv.z + (ev.z - xv.z);
        qv.w = xv.w + (ev.w - xv.w);
        out4[(size_t)(R0 + r) * 64 + c4] = qv;
        float d0 = ev.x - xv.x, d1 = ev.y - xv.y, d2 = ev.z - xv.z, d3 = ev.w - xv.w;
        sse = fmaf(d0, d0, sse); sse = fmaf(d1, d1, sse);
        sse = fmaf(d2, d2, sse); sse = fmaf(d3, d3, sse);
    }
    dred[tid] = (double)sse;
    __syncthreads();
    #pragma unroll
    for (int s = 128; s > 0; s >>= 1) {
        if (tid < s) dred[tid] += dred[tid + s];
        __syncthreads();
    }
    if (tid == 0) atomicAdd(&g_sse, dred[0]);
}

// ---------------- segment-sum (after epilogue builds rowlist) ----------------
__global__ void __launch_bounds__(256)
segsum_kernel(const float* __restrict__ inp) {
    int k = blockIdx.x, t = threadIdx.x;
    int beg = g_off[k], cnt = g_cnt_i[k];
    float s = 0.f;
    int j = 0;
    for (; j + 4 <= cnt; j += 4) {
        int r0 = g_rowlist[beg + j],     r1 = g_rowlist[beg + j + 1];
        int r2 = g_rowlist[beg + j + 2], r3 = g_rowlist[beg + j + 3];
        float v0 = inp[(size_t)r0 * DIM + t];
        float v1 = inp[(size_t)r1 * DIM + t];
        float v2 = inp[(size_t)r2 * DIM + t];
        float v3 = inp[(size_t)r3 * DIM + t];
        s += v0; s += v1; s += v2; s += v3;
    }
    for (; j < cnt; j++) s += inp[(size_t)g_rowlist[beg + j] * DIM + t];
    g_embsum[k * DIM + t] = s;
}

// ---------------- ortho via ||E^T E||_F^2 ----------------
__global__ void gram_kernel(const float* __restrict__ emb) {
    __shared__ float sA[64][16];
    __shared__ float sB[64][16];
    __shared__ double sred[256];
    int tx = threadIdx.x & 15;
    int ty = threadIdx.x >> 4;
    int a0 = blockIdx.y * 16;
    int b0 = blockIdx.x * 16;
    float acc = 0.f;
    for (int k0 = 0; k0 < K_CODES; k0 += 64) {
        __syncthreads();
        #pragma unroll
        for (int i = 0; i < 4; i++) {
            int e = threadIdx.x + i * 256;
            int kr = e >> 4, c = e & 15;
            sA[kr][c] = emb[(size_t)(k0 + kr) * DIM + a0 + c];
            sB[kr][c] = emb[(size_t)(k0 + kr) * DIM + b0 + c];
        }
        __syncthreads();
        #pragma unroll 8
        for (int kk = 0; kk < 64; kk++)
            acc = fmaf(sA[kk][ty], sB[kk][tx], acc);
    }
    sred[threadIdx.x] = (double)acc * (double)acc;
    __syncthreads();
    #pragma unroll
    for (int s = 128; s > 0; s >>= 1) {
        if (threadIdx.x < s) sred[threadIdx.x] += sred[threadIdx.x + s];
        __syncthreads();
    }
    if (threadIdx.x == 0) atomicAdd(&g_ortho, sred[0]);
}

// ---------------- ema_b + loss (fused: block 0 also computes loss) ----------------
__global__ void ema_b_kernel(const float* __restrict__ ema_avg, float* __restrict__ out) {
    int k = blockIdx.x;
    int d = threadIdx.x;
    int i = k * DIM + d;
    float navg = 0.99f * ema_avg[i] + 0.01f * g_embsum[i];
    out[OFF_NAVG + i] = navg;
    float cs = (g_ncs[k] + EPS_F) / g_ntotal;
    out[OFF_NEWEMB + i] = navg / cs;

    if (k == 0) {
        __shared__ double sred[256];
        double s = 0.0;
        for (int kk = d; kk < K_CODES; kk += 256) {
            double e = (double)g_ee[kk];
            s += e * e;
        }
        sred[d] = s;
        __syncthreads();
        #pragma unroll
        for (int t = 128; t > 0; t >>= 1) {
            if (d < t) sred[d] += sred[d + t];
            __syncthreads();
        }
        if (d == 0) {
            double o2 = g_ortho - sred[0];
            if (o2 < 0.0) o2 = 0.0;
            float ortho = sqrtf((float)o2);
            float m = (float)(g_sse / (double)((size_t)N_ROWS * DIM));
            out[OFF_LOSS] = (m + 0.25f * m) + 0.09f * ortho;
        }
    }
}

// ---------------- launch ----------------
extern "C" void kernel_launch(void* const* d_in, const int* in_sizes, int n_in,
                              void* d_out, int out_size)
{
    const float* inp     = (const float*)d_in[0];
    const float* emb     = (const float*)d_in[1];
    const float* ema_cs  = (const float*)d_in[2];
    const float* ema_avg = (const float*)d_in[3];
    float* out = (float*)d_out;

    static int inited = 0;
    static cudaStream_t s2;
    static cudaEvent_t ev_root, ev_pe, ev_side;
    if (!inited) {
        cudaFuncSetAttribute(hmma_gemm_kernel,
                             cudaFuncAttributeMaxDynamicSharedMemorySize, SMEM_DYN);
        cudaStreamCreateWithFlags(&s2, cudaStreamNonBlocking);
        cudaEventCreateWithFlags(&ev_root, cudaEventDisableTiming);
        cudaEventCreateWithFlags(&ev_pe,   cudaEventDisableTiming);
        cudaEventCreateWithFlags(&ev_side, cudaEventDisableTiming);
        inited = 1;
    }

    // fork side stream: prep_e + gram (independent of main chain until gemm/loss)
    cudaEventRecord(ev_root, 0);
    cudaStreamWaitEvent(s2, ev_root, 0);
    prep_e_kernel<<<K_CODES / 8, 256, 0, s2>>>(emb);
    cudaEventRecord(ev_pe, s2);
    gram_kernel<<<dim3(16, 16), 256, 0, s2>>>(emb);
    cudaEventRecord(ev_side, s2);

    prep_x_kernel<<<(N_ROWS * DIM) / (256 * 8), 256>>>(inp);
    cudaStreamWaitEvent(0, ev_pe, 0);          // gemm needs g_ea/g_ee/g_cnt_i
    hmma_gemm_kernel<<<N_ROWS / 128, 512, SMEM_DYN>>>();
    rescore2_kernel<<<1024, 256>>>(inp, emb);
    offsets_kernel<<<1, 1024>>>(ema_cs, out);
    epilogue_kernel<<<N_ROWS / 128, 256>>>(inp, emb, out);
    segsum_kernel<<<K_CODES, 256>>>(inp);
    cudaStreamWaitEvent(0, ev_side, 0);        // loss (in ema_b blk0) needs g_ortho
    ema_b_kernel<<<K_CODES, 256>>>(ema_avg, out);
}

// round 15
// speedup vs baseline: 1.0998x; 1.0775x over previous
#include <cuda_runtime.h>
#include <cuda_bf16.h>
#include <cuda_fp16.h>
#include <math.h>
#include <stdint.h>

// ---------------- problem constants ----------------
#define N_ROWS   131072
#define DIM      256
#define K_CODES  1024
#define EPS_F    1e-5f
#define TAU_F    3.5e-4f
#define CAND_W   6.0e-4f
#define FIX_CAP  131072

// output layout (float32 elements), reference return order
#define OFF_Q       0
#define OFF_LOSS    33554432
#define OFF_IDX     33554433
#define OFF_NEWEMB  33685505
#define OFF_NCS     33947649
#define OFF_NAVG    33948673

// ---------------- device scratch ----------------
__device__ float  g_xx[N_ROWS];
__device__ float  g_smin[N_ROWS];
__device__ float  g_ee[K_CODES];
__device__ float  g_counts[K_CODES];
__device__ float  g_embsum[K_CODES*DIM];
__device__ float  g_ncs[K_CODES];
__device__ float  g_ntotal;
__device__ double g_sse;
__device__ double g_ortho;
__device__ int    g_fixcount;
__device__ int    g_fixrows[FIX_CAP];
__device__ int    g_idx[N_ROWS];
__device__ int    g_cnt_i[K_CODES];
__device__ int    g_off[K_CODES];
__device__ int    g_cursor[K_CODES];
__device__ int    g_rowlist[N_ROWS];
__device__ __nv_bfloat16 g_ea[K_CODES*DIM];
__device__ __nv_bfloat16 g_xa[(size_t)N_ROWS*DIM];
__device__ __half g_sc[(size_t)N_ROWS*K_CODES];   // screened scores, fp16

// ---------------- PTX helpers (baseline sm_80+ ISA only) ----------------
__device__ __forceinline__ uint32_t smem_to_u32(const void* p) {
    uint32_t a;
    asm("{ .reg .u64 t; cvta.to.shared.u64 t, %1; cvt.u32.u64 %0, t; }" : "=r"(a) : "l"(p));
    return a;
}
#define CP_ASYNC16(dst, src) \
    asm volatile("cp.async.cg.shared.global [%0], [%1], 16;" :: "r"(dst), "l"(src))
#define CP_COMMIT() asm volatile("cp.async.commit_group;" ::: "memory")
#define CP_WAIT1()  asm volatile("cp.async.wait_group 1;" ::: "memory")

#define LDSM_X4(r, addr) \
    asm volatile("ldmatrix.sync.aligned.m8n8.x4.shared.b16 {%0,%1,%2,%3}, [%4];" \
        : "=r"((r)[0]), "=r"((r)[1]), "=r"((r)[2]), "=r"((r)[3]) : "r"(addr))

#define MMA_BF16(c, a, b0, b1) \
    asm volatile("mma.sync.aligned.m16n8k16.row.col.f32.bf16.bf16.f32 " \
        "{%0,%1,%2,%3},{%4,%5,%6,%7},{%8,%9},{%0,%1,%2,%3};" \
        : "+f"((c)[0]), "+f"((c)[1]), "+f"((c)[2]), "+f"((c)[3]) \
        : "r"((a)[0]), "r"((a)[1]), "r"((a)[2]), "r"((a)[3]), "r"(b0), "r"(b1))

__device__ __forceinline__ uint32_t packhi2(float x, float y) {
    __nv_bfloat16 a = __float2bfloat16_rn(x);
    __nv_bfloat16 b = __float2bfloat16_rn(y);
    return (uint32_t)__bfloat16_as_ushort(a) | ((uint32_t)__bfloat16_as_ushort(b) << 16);
}

// ---------------- prep codes: zero scratch (block 0) + ||e||^2 + bf16 copy ----------------
__global__ void prep_e_kernel(const float* __restrict__ emb) {
    if (blockIdx.x == 0) {
        for (int i = threadIdx.x; i < K_CODES; i += 256) g_cnt_i[i] = 0;
        if (threadIdx.x == 0) { g_sse = 0.0; g_ortho = 0.0; g_fixcount = 0; }
    }
    int warp = (blockIdx.x * blockDim.x + threadIdx.x) >> 5;
    int lane = threadIdx.x & 31;
    if (warp >= K_CODES) return;
    const float4* p = (const float4*)(emb + (size_t)warp * DIM);
    float4 v0 = p[lane * 2];
    float4 v1 = p[lane * 2 + 1];
    float s = 0.f;
    s = fmaf(v0.x,v0.x,s); s = fmaf(v0.y,v0.y,s); s = fmaf(v0.z,v0.z,s); s = fmaf(v0.w,v0.w,s);
    s = fmaf(v1.x,v1.x,s); s = fmaf(v1.y,v1.y,s); s = fmaf(v1.z,v1.z,s); s = fmaf(v1.w,v1.w,s);
    uint4 hi;
    hi.x = packhi2(v0.x, v0.y);
    hi.y = packhi2(v0.z, v0.w);
    hi.z = packhi2(v1.x, v1.y);
    hi.w = packhi2(v1.z, v1.w);
    ((uint4*)(g_ea + (size_t)warp * DIM))[lane] = hi;
    #pragma unroll
    for (int o = 16; o > 0; o >>= 1) s += __shfl_xor_sync(0xffffffffu, s, o);
    if (lane == 0) g_ee[warp] = s;
}

// ---------------- prep inputs: bf16 + ||x||^2 (warp per row) ----------------
__global__ void prep_x_kernel(const float* __restrict__ inp) {
    size_t base = ((size_t)blockIdx.x * 256 + threadIdx.x) * 8;
    const float4* p = (const float4*)(inp + base);
    float4 v0 = p[0], v1 = p[1];
    float s = 0.f;
    s = fmaf(v0.x,v0.x,s); s = fmaf(v0.y,v0.y,s); s = fmaf(v0.z,v0.z,s); s = fmaf(v0.w,v0.w,s);
    s = fmaf(v1.x,v1.x,s); s = fmaf(v1.y,v1.y,s); s = fmaf(v1.z,v1.z,s); s = fmaf(v1.w,v1.w,s);
    uint4 hi;
    hi.x = packhi2(v0.x, v0.y);
    hi.y = packhi2(v0.z, v0.w);
    hi.z = packhi2(v1.x, v1.y);
    hi.w = packhi2(v1.z, v1.w);
    *(uint4*)(g_xa + base) = hi;
    #pragma unroll
    for (int o = 16; o > 0; o >>= 1) s += __shfl_xor_sync(0xffffffffu, s, o);
    int lane = threadIdx.x & 31;
    if (lane == 0) g_xx[blockIdx.x * 8 + (threadIdx.x >> 5)] = s;
}

// ---------------- HMMA GEMM, 256 threads / 64 rows, 2 CTAs per SM ----------------
// smem: XRES[4 kc][64 rows][64 dims] @0 (32K) | E buf b @32768+b*32768 ([2 kcs][128 codes][64 dims])
// score staging ALIASES E buf1 (@65536): safe — written only after buf1's E is consumed,
// dumped before buf1 is reloaded (barriers enforce both).
#define OFB_E  32768
#define E_STRIDE 32768
#define STG_OFF 65536
#define SMEM_DYN (98304 + 1024)

__device__ __forceinline__ void load_x_res(uint32_t sbase, int R0, int tid) {
    const __nv_bfloat16* xa = g_xa + ((size_t)R0 << 8);
    #pragma unroll
    for (int it = 0; it < 8; it++) {
        int idx = tid + it * 256;           // 0..2047
        int kc  = idx >> 9;                 // 64-dim chunk 0..3
        int rem = idx & 511;
        int r = rem >> 3, kb = rem & 7;     // r: 0..63
        uint32_t sw = (((uint32_t)kb * 16u) ^ (((uint32_t)r & 7u) * 16u));
        uint32_t d  = sbase + (uint32_t)kc * 8192u + (uint32_t)r * 128u + sw;
        CP_ASYNC16(d, xa + (size_t)r * DIM + kc * 64 + kb * 8);
    }
}

__device__ __forceinline__ void load_e_stage(uint32_t sbase, int st, int tid) {
    int n0 = st >> 1, kc2 = st & 1;
    uint32_t ebase = sbase + OFB_E + (uint32_t)(st & 1) * E_STRIDE;
    const __nv_bfloat16* ea = g_ea + ((size_t)(n0 * 128) << 8) + kc2 * 128;
    #pragma unroll
    for (int it = 0; it < 8; it++) {
        int idx = tid + it * 256;           // 0..2047
        int kcs = idx >> 10;                // sub-chunk 0/1
        int rem = idx & 1023;
        int r = rem >> 3, kb = rem & 7;     // r: 0..127 codes
        uint32_t sw = (((uint32_t)kb * 16u) ^ (((uint32_t)r & 7u) * 16u));
        uint32_t d  = ebase + (uint32_t)kcs * 16384u + (uint32_t)r * 128u + sw;
        CP_ASYNC16(d, ea + (size_t)r * DIM + kcs * 64 + kb * 8);
    }
}

__global__ void __launch_bounds__(256, 2)
hmma_gemm_kernel()
{
    extern __shared__ __align__(16) char dsm[];
    uint32_t raw   = smem_to_u32(dsm);
    uint32_t sbase = (raw + 1023u) & ~1023u;
    char*    smema = dsm + (sbase - raw);

    const int tid  = threadIdx.x;
    const int lane = tid & 31, wid = tid >> 5;
    const int wr   = wid >> 2, wc = wid & 3;    // wr: 32-row group (0..1), wc: 32-code group (0..3)
    const int R0   = blockIdx.x * 64;
    const int g    = lane >> 2, tig = lane & 3;
    const int q    = lane >> 3, lr  = lane & 7;

    float acc[2][4][4];
    #pragma unroll
    for (int a = 0; a < 2; a++)
        #pragma unroll
        for (int b = 0; b < 4; b++)
            #pragma unroll
            for (int c = 0; c < 4; c++) acc[a][b][c] = 0.f;

    float rs1[4], rs2[4]; int ri[4];
    #pragma unroll
    for (int j = 0; j < 4; j++) { rs1[j] = 3.0e38f; rs2[j] = 3.0e38f; ri[j] = 0x7fffffff; }

    uint32_t* stage_w = (uint32_t*)(smema + STG_OFF);   // row stride = 68 words (272B)

    load_x_res(sbase, R0, tid);
    load_e_stage(sbase, 0, tid);
    CP_COMMIT();                   // group A: X + E0

    for (int s = 0; s < 16; s++) {
        if (s + 1 < 16) load_e_stage(sbase, s + 1, tid);
        CP_COMMIT();
        CP_WAIT1();                // stage s (and X) resident
        __syncthreads();

        const int kc2 = s & 1;
        uint32_t ebase = sbase + OFB_E + (uint32_t)(s & 1) * E_STRIDE;
        #pragma unroll
        for (int kcs = 0; kcs < 2; kcs++) {
            uint32_t xbase = sbase + (uint32_t)(kc2 * 2 + kcs) * 8192u;
            uint32_t ecb   = ebase + (uint32_t)kcs * 16384u;
            #pragma unroll
            for (int ks = 0; ks < 4; ks++) {
                uint32_t axa[8];
                int rowb = wr * 32 + lr + ((q & 1) << 3);
                int kbA  = ks * 2 + (q >> 1);
                uint32_t swA = (((uint32_t)kbA * 16u) ^ ((uint32_t)lr * 16u));
                #pragma unroll
                for (int mf = 0; mf < 2; mf++) {
                    uint32_t ad = xbase + (uint32_t)(rowb + mf * 16) * 128u + swA;
                    LDSM_X4(&axa[mf * 4], ad);
                }
                uint32_t bea[8];
                int kbB = ks * 2 + (q & 1);
                uint32_t swB = (((uint32_t)kbB * 16u) ^ ((uint32_t)lr * 16u));
                #pragma unroll
                for (int np = 0; np < 2; np++) {
                    int code = wc * 32 + np * 16 + lr + ((q >> 1) << 3);
                    uint32_t ed = ecb + (uint32_t)code * 128u + swB;
                    LDSM_X4(&bea[np * 4], ed);
                }
                #pragma unroll
                for (int mf = 0; mf < 2; mf++)
                    #pragma unroll
                    for (int nf = 0; nf < 4; nf++) {
                        int bo = (nf >> 1) * 4 + (nf & 1) * 2;
                        MMA_BF16(acc[mf][nf], &axa[mf * 4], bea[bo], bea[bo + 1]);
                    }
            }
        }

        if (s & 1) {
            __syncthreads();       // all warps done reading E buf1 before staging aliases it
            int n0 = s >> 1;
            float ee8[8];
            #pragma unroll
            for (int nf = 0; nf < 4; nf++) {
                int code = n0 * 128 + wc * 32 + nf * 8 + tig * 2;
                ee8[nf * 2]     = __ldg(&g_ee[code]);
                ee8[nf * 2 + 1] = __ldg(&g_ee[code + 1]);
            }
            #pragma unroll
            for (int mf = 0; mf < 2; mf++)
                #pragma unroll
                for (int h = 0; h < 2; h++) {
                    int j = mf * 2 + h;
                    int row = wr * 32 + mf * 16 + h * 8 + g;
                    float b1 = 3.0e38f, b2 = 3.0e38f; int bi = 0;
                    #pragma unroll
                    for (int nf = 0; nf < 4; nf++) {
                        int code = n0 * 128 + wc * 32 + nf * 8 + tig * 2;
                        float s0 = fmaf(-2.f, acc[mf][nf][h * 2],     ee8[nf * 2]);
                        float s1 = fmaf(-2.f, acc[mf][nf][h * 2 + 1], ee8[nf * 2 + 1]);
                        __half2 hv = __floats2half2_rn(s0, s1);
                        stage_w[row * 68 + wc * 16 + nf * 4 + tig] = *(uint32_t*)&hv;
                        if (s0 < b1) { b2 = b1; b1 = s0; bi = code; }
                        else if (s0 < b2) b2 = s0;
                        if (s1 < b1) { b2 = b1; b1 = s1; bi = code + 1; }
                        else if (s1 < b2) b2 = s1;
                    }
                    #pragma unroll
                    for (int off = 1; off <= 2; off <<= 1) {
                        float o1 = __shfl_xor_sync(0xffffffffu, b1, off);
                        float o2 = __shfl_xor_sync(0xffffffffu, b2, off);
                        int   oi = __shfl_xor_sync(0xffffffffu, bi, off);
                        if (o1 < b1) { b2 = fminf(b1, o2); b1 = o1; bi = oi; }
                        else         { b2 = fminf(b2, o1); }
                    }
                    if (b1 < rs1[j]) { rs2[j] = fminf(rs1[j], b2); rs1[j] = b1; ri[j] = bi; }
                    else             { rs2[j] = fminf(rs2[j], b1); }
                }
            __syncthreads();
            // coalesced copy staging -> g_sc[row][n0*128 .. +128)
            #pragma unroll
            for (int it = 0; it < 4; it++) {
                int idx = tid + it * 256;          // 0..1023
                int row = idx >> 4, seg = idx & 15;
                uint4 v = *(const uint4*)(smema + STG_OFF + row * 272 + seg * 16);
                *(uint4*)((char*)(g_sc + (size_t)(R0 + row) * K_CODES + n0 * 128) + seg * 16) = v;
            }
            #pragma unroll
            for (int a = 0; a < 2; a++)
                #pragma unroll
                for (int b = 0; b < 4; b++)
                    #pragma unroll
                    for (int c = 0; c < 4; c++) acc[a][b][c] = 0.f;
        }
        __syncthreads();
    }

    // final cross-warp merge (alias XRES smem; all MMA work done)
    float* fs1 = (float*)smema;
    float* fs2 = (float*)(smema + 1024);
    int*   fi1 = (int*)  (smema + 2048);
    #pragma unroll
    for (int mf = 0; mf < 2; mf++)
        #pragma unroll
        for (int h = 0; h < 2; h++) {
            int j = mf * 2 + h;
            int row = wr * 32 + mf * 16 + h * 8 + g;
            fs1[row * 4 + wc] = rs1[j];
            fs2[row * 4 + wc] = rs2[j];
            fi1[row * 4 + wc] = ri[j];
        }
    __syncthreads();
    if (tid < 64) {
        float b1 = 3.0e38f, b2 = 3.0e38f; int bi = 0;
        #pragma unroll
        for (int w = 0; w < 4; w++) {
            float o1 = fs1[tid * 4 + w], o2 = fs2[tid * 4 + w];
            int   oi = fi1[tid * 4 + w];
            if (o1 < b1) { b2 = fminf(b1, o2); b1 = o1; bi = oi; }
            else         { b2 = fminf(b2, o1); }
        }
        g_idx[R0 + tid] = bi;
        g_smin[R0 + tid] = b1;                      // screened min for rescore threshold
        atomicAdd(&g_cnt_i[bi], 1);                 // tentative histogram
        if (b2 - b1 < TAU_F) {
            int p = atomicAdd(&g_fixcount, 1);
            if (p < FIX_CAP) g_fixrows[p] = R0 + tid;
        }
    }
}

// ---------------- candidate rescore: warp per flagged row (uses g_smin, no min-scan) ----------------
__global__ void __launch_bounds__(256)
rescore2_kernel(const float* __restrict__ inp, const float* __restrict__ emb)
{
    int n = g_fixcount; if (n > FIX_CAP) n = FIX_CAP;
    int gw   = (blockIdx.x * 256 + threadIdx.x) >> 5;
    int lane = threadIdx.x & 31;
    const int NW = (1024 * 256) >> 5;

    for (int fi = gw; fi < n; fi += NW) {
        int row = g_fixrows[fi];
        const __half* sc = g_sc + (size_t)row * K_CODES;
        float thr = g_smin[row] + CAND_W;

        const float4* xr = (const float4*)(inp + (size_t)row * DIM);
        float4 xa = xr[lane * 2], xb = xr[lane * 2 + 1];
        float xx = g_xx[row];

        float bd = 3.0e38f; int bi = 0x7fffffff;
        for (int ci = 0; ci < 32; ci++) {
            float sv = __half2float(sc[ci * 32 + lane]);
            unsigned mask = __ballot_sync(0xffffffffu, sv <= thr);
            while (mask) {
                int b_ = __ffs(mask) - 1; mask &= mask - 1;
                int cc = ci * 32 + b_;
                const float4* er = (const float4*)(emb + (size_t)cc * DIM);
                float4 e0 = er[lane * 2], e1 = er[lane * 2 + 1];
                float d = 0.f;
                d = fmaf(e0.x, xa.x, d); d = fmaf(e0.y, xa.y, d);
                d = fmaf(e0.z, xa.z, d); d = fmaf(e0.w, xa.w, d);
                d = fmaf(e1.x, xb.x, d); d = fmaf(e1.y, xb.y, d);
                d = fmaf(e1.z, xb.z, d); d = fmaf(e1.w, xb.w, d);
                #pragma unroll
                for (int o = 16; o > 0; o >>= 1) d += __shfl_xor_sync(0xffffffffu, d, o);
                float dist = (xx + g_ee[cc]) - 2.0f * d;
                if (dist < bd || (dist == bd && cc < bi)) { bd = dist; bi = cc; }
            }
        }
        if (lane == 0) {
            int old = g_idx[row];
            if (bi != old) {
                g_idx[row] = bi;
                atomicAdd(&g_cnt_i[old], -1);
                atomicAdd(&g_cnt_i[bi], 1);
            }
        }
    }
}

// ---------------- offsets + ema_a (fused) ----------------
__global__ void offsets_kernel(const float* __restrict__ ema_cs, float* __restrict__ out) {
    __shared__ int tmp[2][1024];
    __shared__ double sred[1024];
    int t = threadIdx.x;
    int v = g_cnt_i[t];
    g_counts[t] = (float)v;
    tmp[0][t] = v;
    __syncthreads();
    int src = 0;
    #pragma unroll
    for (int d = 1; d < 1024; d <<= 1) {
        int nv = tmp[src][t] + (t >= d ? tmp[src][t - d] : 0);
        tmp[src ^ 1][t] = nv;
        src ^= 1;
        __syncthreads();
    }
    int off = tmp[src][t] - v;   // exclusive
    g_off[t] = off;
    g_cursor[t] = off;

    // ---- fused ema_a ----
    float ncs = 0.99f * ema_cs[t] + 0.01f * (float)v;
    out[OFF_NCS + t] = ncs;
    g_ncs[t] = ncs;
    sred[t] = (double)ncs;
    __syncthreads();
    #pragma unroll
    for (int s = 512; s > 0; s >>= 1) {
        if (t < s) sred[t] += sred[t + s];
        __syncthreads();
    }
    if (t == 0) g_ntotal = (float)sred[0] + EPS_F;
}

// ---------------- epilogue: gather + Q/idx output + MSE + rowlist scatter ----------------
__global__ void __launch_bounds__(256)
epilogue_kernel(const float* __restrict__ inp, const float* __restrict__ emb,
                float* __restrict__ out)
{
    __shared__ int besti[128];
    __shared__ double dred[256];
    const int tid = threadIdx.x;
    const int R0  = blockIdx.x * 128;
    if (tid < 128) {
        int v = g_idx[R0 + tid];
        besti[tid] = v;
        out[OFF_IDX + R0 + tid] = (float)v;
        int pos = atomicAdd(&g_cursor[v], 1);      // fused scatter
        g_rowlist[pos] = R0 + tid;
    }
    __syncthreads();

    float sse = 0.f;
    const float4* inp4 = (const float4*)inp;
    const float4* emb4 = (const float4*)emb;
    float4* out4 = (float4*)(out + OFF_Q);
    #pragma unroll 4
    for (int j = 0; j < 32; j++) {
        int e4  = tid + j * 256;
        int r   = e4 >> 6;
        int c4  = e4 & 63;
        int idx = besti[r];
        float4 ev = emb4[idx * 64 + c4];
        float4 xv = inp4[(size_t)(R0 + r) * 64 + c4];
        float4 qv;
        qv.x = xv.x + (ev.x - xv.x);
        qv.y = xv.y + (ev.y - xv.y);
        qv.z = xv.z + (ev.z - xv.z);
        qv.w = xv.w + (ev.w - xv.w);
        out4[(size_t)(R0 + r) * 64 + c4] = qv;
        float d0 = ev.x - xv.x, d1 = ev.y - xv.y, d2 = ev.z - xv.z, d3 = ev.w - xv.w;
        sse = fmaf(d0, d0, sse); sse = fmaf(d1, d1, sse);
        sse = fmaf(d2, d2, sse); sse = fmaf(d3, d3, sse);
    }
    dred[tid] = (double)sse;
    __syncthreads();
    #pragma unroll
    for (int s = 128; s > 0; s >>= 1) {
        if (tid < s) dred[tid] += dred[tid + s];
        __syncthreads();
    }
    if (tid == 0) atomicAdd(&g_sse, dred[0]);
}

// ---------------- segment-sum (after epilogue builds rowlist) ----------------
__global__ void __launch_bounds__(256)
segsum_kernel(const float* __restrict__ inp) {
    int k = blockIdx.x, t = threadIdx.x;
    int beg = g_off[k], cnt = g_cnt_i[k];
    float s = 0.f;
    int j = 0;
    for (; j + 4 <= cnt; j += 4) {
        int r0 = g_rowlist[beg + j],     r1 = g_rowlist[beg + j + 1];
        int r2 = g_rowlist[beg + j + 2], r3 = g_rowlist[beg + j + 3];
        float v0 = inp[(size_t)r0 * DIM + t];
        float v1 = inp[(size_t)r1 * DIM + t];
        float v2 = inp[(size_t)r2 * DIM + t];
        float v3 = inp[(size_t)r3 * DIM + t];
        s += v0; s += v1; s += v2; s += v3;
    }
    for (; j < cnt; j++) s += inp[(size_t)g_rowlist[beg + j] * DIM + t];
    g_embsum[k * DIM + t] = s;
}

// ---------------- ortho via ||E^T E||_F^2 ----------------
__global__ void gram_kernel(const float* __restrict__ emb) {
    __shared__ float sA[64][16];
    __shared__ float sB[64][16];
    __shared__ double sred[256];
    int tx = threadIdx.x & 15;
    int ty = threadIdx.x >> 4;
    int a0 = blockIdx.y * 16;
    int b0 = blockIdx.x * 16;
    float acc = 0.f;
    for (int k0 = 0; k0 < K_CODES; k0 += 64) {
        __syncthreads();
        #pragma unroll
        for (int i = 0; i < 4; i++) {
            int e = threadIdx.x + i * 256;
            int kr = e >> 4, c = e & 15;
            sA[kr][c] = emb[(size_t)(k0 + kr) * DIM + a0 + c];
            sB[kr][c] = emb[(size_t)(k0 + kr) * DIM + b0 + c];
        }
        __syncthreads();
        #pragma unroll 8
        for (int kk = 0; kk < 64; kk++)
            acc = fmaf(sA[kk][ty], sB[kk][tx], acc);
    }
    sred[threadIdx.x] = (double)acc * (double)acc;
    __syncthreads();
    #pragma unroll
    for (int s = 128; s > 0; s >>= 1) {
        if (threadIdx.x < s) sred[threadIdx.x] += sred[threadIdx.x + s];
        __syncthreads();
    }
    if (threadIdx.x == 0) atomicAdd(&g_ortho, sred[0]);
}

// ---------------- ema_b + loss (fused: block 0 also computes loss) ----------------
__global__ void ema_b_kernel(const float* __restrict__ ema_avg, float* __restrict__ out) {
    int k = blockIdx.x;
    int d = threadIdx.x;
    int i = k * DIM + d;
    float navg = 0.99f * ema_avg[i] + 0.01f * g_embsum[i];
    out[OFF_NAVG + i] = navg;
    float cs = (g_ncs[k] + EPS_F) / g_ntotal;
    out[OFF_NEWEMB + i] = navg / cs;

    if (k == 0) {
        __shared__ double sred[256];
        double s = 0.0;
        for (int kk = d; kk < K_CODES; kk += 256) {
            double e = (double)g_ee[kk];
            s += e * e;
        }
        sred[d] = s;
        __syncthreads();
        #pragma unroll
        for (int t = 128; t > 0; t >>= 1) {
            if (d < t) sred[d] += sred[d + t];
            __syncthreads();
        }
        if (d == 0) {
            double o2 = g_ortho - sred[0];
            if (o2 < 0.0) o2 = 0.0;
            float ortho = sqrtf((float)o2);
            float m = (float)(g_sse / (double)((size_t)N_ROWS * DIM));
            out[OFF_LOSS] = (m + 0.25f * m) + 0.09f * ortho;
        }
    }
}

// ---------------- launch ----------------
extern "C" void kernel_launch(void* const* d_in, const int* in_sizes, int n_in,
                              void* d_out, int out_size)
{
    const float* inp     = (const float*)d_in[0];
    const float* emb     = (const float*)d_in[1];
    const float* ema_cs  = (const float*)d_in[2];
    const float* ema_avg = (const float*)d_in[3];
    float* out = (float*)d_out;

    static int inited = 0;
    static cudaStream_t s2;
    static cudaEvent_t ev_root, ev_pe, ev_side;
    if (!inited) {
        cudaFuncSetAttribute(hmma_gemm_kernel,
                             cudaFuncAttributeMaxDynamicSharedMemorySize, SMEM_DYN);
        cudaStreamCreateWithFlags(&s2, cudaStreamNonBlocking);
        cudaEventCreateWithFlags(&ev_root, cudaEventDisableTiming);
        cudaEventCreateWithFlags(&ev_pe,   cudaEventDisableTiming);
        cudaEventCreateWithFlags(&ev_side, cudaEventDisableTiming);
        inited = 1;
    }

    // fork side stream: prep_e + gram (independent of main chain until gemm/loss)
    cudaEventRecord(ev_root, 0);
    cudaStreamWaitEvent(s2, ev_root, 0);
    prep_e_kernel<<<K_CODES / 8, 256, 0, s2>>>(emb);
    cudaEventRecord(ev_pe, s2);
    gram_kernel<<<dim3(16, 16), 256, 0, s2>>>(emb);
    cudaEventRecord(ev_side, s2);

    prep_x_kernel<<<(N_ROWS * DIM) / (256 * 8), 256>>>(inp);
    cudaStreamWaitEvent(0, ev_pe, 0);          // gemm needs g_ea/g_ee/g_cnt_i
    hmma_gemm_kernel<<<N_ROWS / 64, 256, SMEM_DYN>>>();
    rescore2_kernel<<<1024, 256>>>(inp, emb);
    offsets_kernel<<<1, 1024>>>(ema_cs, out);
    epilogue_kernel<<<N_ROWS / 128, 256>>>(inp, emb, out);
    segsum_kernel<<<K_CODES, 256>>>(inp);
    cudaStreamWaitEvent(0, ev_side, 0);        // loss (in ema_b blk0) needs g_ortho
    ema_b_kernel<<<K_CODES, 256>>>(ema_avg, out);
}